// round 8
// baseline (speedup 1.0000x reference)
#include <cuda_runtime.h>
#include <math.h>
#include <stdint.h>

// ---------------- problem constants ----------------
#define BB    16
#define TT    32
#define CC    3
#define HH    64
#define WW    64
#define DD    512
#define LL    6
#define BT    512          // B*T
#define NTOK  64           // tokens per frame (8x8)
#define M_CONV 32768       // B*T*NTOK
#define K_CONV 576         // C*KT*P*P
#define EPSV  1e-5f

#define SA    20           // As row stride (floats)
#define SB    72           // Bs row stride (floats)

// ---------------- scratch (device globals; no allocation) ----------------
__device__ float g_tok[M_CONV * DD];
__device__ float g_wT [K_CONV * DD];
__device__ float g_h  [BT * DD];
__device__ float g_kqv[BT * 3 * DD];
__device__ float g_yv [BT * DD];
__device__ float g_mid[BT * 4 * DD];
// LN-folded weights + epilogue vectors
__device__ float g_w1s[LL * DD * 3 * DD];   // lng1-scaled kqv weights
__device__ float g_w2s[LL * DD * 4 * DD];   // lng2-scaled mlp1 weights
__device__ float g_c1 [LL * 3 * DD];
__device__ float g_d1 [LL * 3 * DD];
__device__ float g_c2 [LL * 4 * DD];
__device__ float g_d2 [LL * 4 * DD];
// RoPE table
__device__ float g_ropes[TT * 32];
__device__ float g_ropec[TT * 32];

// ---------------- helpers ----------------
__device__ __forceinline__ uint32_t f2tf(float f) {
    uint32_t u;
    asm("cvt.rna.tf32.f32 %0, %1;" : "=r"(u) : "f"(f));
    return u;
}

__device__ __forceinline__ void mma1688(float* c, const uint32_t* a, const uint32_t* b) {
    asm volatile(
        "mma.sync.aligned.m16n8k8.row.col.f32.tf32.tf32.f32 "
        "{%0,%1,%2,%3}, {%4,%5,%6,%7}, {%8,%9}, {%0,%1,%2,%3};"
        : "+f"(c[0]), "+f"(c[1]), "+f"(c[2]), "+f"(c[3])
        : "r"(a[0]), "r"(a[1]), "r"(a[2]), "r"(a[3]), "r"(b[0]), "r"(b[1]));
}

__device__ __forceinline__ void cp16(void* smem, const void* gmem) {
    uint32_t s = (uint32_t)__cvta_generic_to_shared(smem);
    asm volatile("cp.async.cg.shared.global [%0], [%1], 16;\n" :: "r"(s), "l"(gmem));
}
__device__ __forceinline__ void cp16z(void* smem, const void* gmem, bool pred) {
    uint32_t s = (uint32_t)__cvta_generic_to_shared(smem);
    int sz = pred ? 16 : 0;
    asm volatile("cp.async.cg.shared.global [%0], [%1], 16, %2;\n" :: "r"(s), "l"(gmem), "r"(sz));
}
__device__ __forceinline__ void cp_commit() {
    asm volatile("cp.async.commit_group;\n");
}
template<int N>
__device__ __forceinline__ void cp_wait() {
    asm volatile("cp.async.wait_group %0;\n" :: "n"(N));
}

// ---------------- weight transpose ----------------
__global__ void transpose_w_kernel(const float* __restrict__ w) {
    int idx = blockIdx.x * 256 + threadIdx.x;
    if (idx < DD * K_CONV) {
        int d = idx / K_CONV, k = idx - d * K_CONV;
        g_wT[k * DD + d] = w[idx];
    }
}

// ---------------- RoPE table ----------------
__global__ void rope_kernel() {
    int tid = threadIdx.x;          // 1024 threads
    int t = tid >> 5, d0 = tid & 31;
    float freq = exp2f(-(float)d0 * (13.287712379549449f / 32.f));
    float ang = (float)t * freq;
    float s, c;
    sincosf(ang, &s, &c);
    g_ropes[tid] = s;
    g_ropec[tid] = c;
}

// ---------------- LN weight folding prep ----------------
// For layer l, column n: Wout[k,n] = lng[k]*W[k,n];
//   C[n] = bias[n] + sum_k lnb[k]*W[k,n];  D[n] = sum_k lng[k]*W[k,n]
__global__ __launch_bounds__(256) void prep_lnw_kernel(
    const float* __restrict__ W, const float* __restrict__ lng,
    const float* __restrict__ lnb, const float* __restrict__ bias,
    float* __restrict__ Wout, float* __restrict__ C, float* __restrict__ D, int N)
{
    __shared__ float gs[DD], bs[DD];
    int l = blockIdx.y;
    int tid = threadIdx.x;
    int n = blockIdx.x * 256 + tid;
    gs[tid] = lng[l * DD + tid];       gs[tid + 256] = lng[l * DD + tid + 256];
    bs[tid] = lnb[l * DD + tid];       bs[tid + 256] = lnb[l * DD + tid + 256];
    __syncthreads();
    const float* Wl = W + (size_t)l * DD * N;
    float* Wo = Wout + (size_t)l * DD * N;
    float accC = bias[l * N + n], accD = 0.f;
    #pragma unroll 8
    for (int k = 0; k < DD; k++) {
        float w = Wl[(size_t)k * N + n];
        float gw = gs[k] * w;
        accC = fmaf(bs[k], w, accC);
        accD += gw;
        Wo[(size_t)k * N + n] = gw;
    }
    C[l * N + n] = accC;
    D[l * N + n] = accD;
}

// ---- warp tile 32x32 (2 m16 x 4 n8) for conv ----
__device__ __forceinline__ void mma_tile_f32(
    const float* As, const float* Bs, int warp_m, int warp_n, int lane, float c[2][4][4])
{
    int g  = lane >> 2;
    int tg = lane & 3;
    #pragma unroll
    for (int ks = 0; ks < 16; ks += 8) {
        uint32_t a[2][4], b[4][2];
        #pragma unroll
        for (int mt = 0; mt < 2; mt++) {
            int r0 = warp_m + mt * 16 + g;
            a[mt][0] = f2tf(As[(r0    ) * SA + ks + tg    ]);
            a[mt][1] = f2tf(As[(r0 + 8) * SA + ks + tg    ]);
            a[mt][2] = f2tf(As[(r0    ) * SA + ks + tg + 4]);
            a[mt][3] = f2tf(As[(r0 + 8) * SA + ks + tg + 4]);
        }
        #pragma unroll
        for (int nt = 0; nt < 4; nt++) {
            int col = warp_n + nt * 8 + g;
            b[nt][0] = f2tf(Bs[(ks + tg    ) * SB + col]);
            b[nt][1] = f2tf(Bs[(ks + tg + 4) * SB + col]);
        }
        #pragma unroll
        for (int mt = 0; mt < 2; mt++)
            #pragma unroll
            for (int nt = 0; nt < 4; nt++)
                mma1688(c[mt][nt], a[mt], b[nt]);
    }
}

// ---- warp tile 32x16 (2 m16 x 2 n8) for transformer GEMMs ----
__device__ __forceinline__ void mma_tile32(
    const float* As, const float* Bs, int warp_n, int lane, float c[2][2][4])
{
    int g  = lane >> 2;
    int tg = lane & 3;
    #pragma unroll
    for (int ks = 0; ks < 16; ks += 8) {
        uint32_t a[2][4], b[2][2];
        #pragma unroll
        for (int mt = 0; mt < 2; mt++) {
            int r0 = mt * 16 + g;
            a[mt][0] = f2tf(As[(r0    ) * SA + ks + tg    ]);
            a[mt][1] = f2tf(As[(r0 + 8) * SA + ks + tg    ]);
            a[mt][2] = f2tf(As[(r0    ) * SA + ks + tg + 4]);
            a[mt][3] = f2tf(As[(r0 + 8) * SA + ks + tg + 4]);
        }
        #pragma unroll
        for (int nt = 0; nt < 2; nt++) {
            int col = warp_n + nt * 8 + g;
            b[nt][0] = f2tf(Bs[(ks + tg    ) * SB + col]);
            b[nt][1] = f2tf(Bs[(ks + tg + 4) * SB + col]);
        }
        #pragma unroll
        for (int mt = 0; mt < 2; mt++)
            #pragma unroll
            for (int nt = 0; nt < 2; nt++)
                mma1688(c[mt][nt], a[mt], b[nt]);
    }
}

// ---------------- conv as GEMM (im2col, tf32 TC, 3-stage cp.async) --------
__global__ __launch_bounds__(256) void conv_gemm_tc(
    const float* __restrict__ x, const float* __restrict__ bias)
{
    constexpr int BM = 128;
    constexpr int ST = 3;
    __shared__ float As[ST][BM * SA];
    __shared__ float Bs[ST][16 * SB];
    int tid = threadIdx.x;
    int warp = tid >> 5, lane = tid & 31;
    int m0 = blockIdx.y * BM, n0 = blockIdx.x * 64;

    int kk = (tid & 3) << 2;
    const float* xb[2];
    int trow[2], arow[2];
    #pragma unroll
    for (int p = 0; p < 2; p++) {
        int row = p * 64 + (tid >> 2);
        arow[p] = row;
        int m = m0 + row;
        int b = m >> 11;
        int t = (m >> 6) & 31;
        int n = m & 63;
        int hn = n >> 3, wn = n & 7;
        xb[p]  = x + b * (TT * CC * HH * WW) + (hn * 8) * WW + wn * 8;
        trow[p] = t;
    }

    int nb = (tid & 15) << 2;
    int kb = tid >> 4;
    const float* Wp = g_wT + kb * DD + n0 + nb;

    constexpr int NIT = K_CONV / 16;

    auto issue = [&](int it) {
        int slot = it % ST;
        float* as = As[slot];
        float* bs = Bs[slot];
        int kg  = it * 16 + kk;
        int cch = kg / 192;
        int r   = kg - cch * 192;
        int dt  = r >> 6;
        int pix = r & 63;
        int ph  = pix >> 3, pw = pix & 7;
        #pragma unroll
        for (int p = 0; p < 2; p++) {
            int tin = trow[p] + dt - 2;
            bool ok = (tin >= 0);
            const float* src = xb[p] + (ok ? tin : 0) * (CC * HH * WW) + cch * (HH * WW) + ph * WW + pw;
            cp16z(&as[arow[p] * SA + kk], src, ok);
        }
        cp16(&bs[kb * SB + nb], Wp + (size_t)(it * 16) * DD);
        cp_commit();
    };

    issue(0); issue(1);

    int warp_m = (warp >> 1) * 32, warp_n = (warp & 1) * 32;
    float c[2][4][4] = {};
    for (int it = 0; it < NIT; it++) {
        cp_wait<1>();
        __syncthreads();
        mma_tile_f32(As[it % ST], Bs[it % ST], warp_m, warp_n, lane, c);
        if (it + ST - 1 < NIT) issue(it + ST - 1);
        else cp_commit();
    }

    int g = lane >> 2, tg = lane & 3;
    #pragma unroll
    for (int mt = 0; mt < 2; mt++) {
        #pragma unroll
        for (int nt = 0; nt < 4; nt++) {
            int cb = n0 + warp_n + nt * 8 + 2 * tg;
            float b0 = bias[cb], b1 = bias[cb + 1];
            int r0 = m0 + warp_m + mt * 16 + g;
            *(float2*)&g_tok[(size_t)r0 * DD + cb]       = make_float2(c[mt][nt][0] + b0, c[mt][nt][1] + b1);
            *(float2*)&g_tok[(size_t)(r0 + 8) * DD + cb] = make_float2(c[mt][nt][2] + b0, c[mt][nt][3] + b1);
        }
    }
}

// ---------------- transformer GEMM: BM=32, BN=64, 128 thr, 4-stage -------
// EPI 0: out = A@W + bias ; EPI 1: gelu(.) ; EPI 2: res + (*scale_p)*(.)
template<int EPI>
__global__ __launch_bounds__(128) void gemm_tc(
    const float* __restrict__ A, const float* __restrict__ W,
    const float* __restrict__ bias, const float* __restrict__ res,
    const float* __restrict__ scale_p, float* __restrict__ out,
    int M, int N, int K)
{
    constexpr int BM = 32;
    constexpr int ST = 4;
    __shared__ float As[ST][BM * SA];
    __shared__ float Bs[ST][16 * SB];
    int tid = threadIdx.x;
    int warp = tid >> 5, lane = tid & 31;
    int m0 = blockIdx.y * BM, n0 = blockIdx.x * 64;

    int kk = (tid & 3) << 2;
    int a_r = tid >> 2;
    const float* Ap = A + (size_t)(m0 + a_r) * K + kk;
    int nb = (tid & 15) << 2;
    int kb = tid >> 4;
    const float* Wp = W + (size_t)kb * N + n0 + nb;

    int NIT = K / 16;

    auto issue = [&](int it) {
        int slot = it % ST;
        int k0 = it * 16;
        cp16(&As[slot][a_r * SA + kk],       Ap + k0);
        cp16(&Bs[slot][kb * SB + nb],        Wp + (size_t)k0 * N);
        cp16(&Bs[slot][(kb + 8) * SB + nb],  Wp + (size_t)(k0 + 8) * N);
        cp_commit();
    };

    issue(0); issue(1); issue(2);

    int warp_n = warp * 16;
    float c[2][2][4] = {};
    for (int it = 0; it < NIT; it++) {
        cp_wait<2>();
        __syncthreads();
        mma_tile32(As[it % ST], Bs[it % ST], warp_n, lane, c);
        if (it + ST - 1 < NIT) issue(it + ST - 1);
        else cp_commit();
    }

    float s = (EPI == 2) ? *scale_p : 0.f;
    int g = lane >> 2, tg = lane & 3;
    #pragma unroll
    for (int mt = 0; mt < 2; mt++) {
        #pragma unroll
        for (int nt = 0; nt < 2; nt++) {
            int cb = n0 + warp_n + nt * 8 + 2 * tg;
            float b0 = bias[cb], b1 = bias[cb + 1];
            #pragma unroll
            for (int h = 0; h < 2; h++) {
                int r = m0 + mt * 16 + g + h * 8;
                float v0 = c[mt][nt][2 * h]     + b0;
                float v1 = c[mt][nt][2 * h + 1] + b1;
                if (EPI == 1) {
                    v0 = 0.5f * v0 * (1.0f + erff(v0 * 0.70710678118654752f));
                    v1 = 0.5f * v1 * (1.0f + erff(v1 * 0.70710678118654752f));
                }
                if (EPI == 2) {
                    v0 = res[(size_t)r * N + cb]     + s * v0;
                    v1 = res[(size_t)r * N + cb + 1] + s * v1;
                }
                *(float2*)&out[(size_t)r * N + cb] = make_float2(v0, v1);
            }
        }
    }
}

// -------- LN-folded transformer GEMM: out = [gelu?]( rs*(A@W') + C - mu*rs*D )
// A = raw h; W' pre-scaled by lng; C/D precomputed vectors. K = DD.
template<int EPI>   // 0 plain, 1 gelu
__global__ __launch_bounds__(128) void gemm_lnw_tc(
    const float* __restrict__ A, const float* __restrict__ W,
    const float* __restrict__ Cv, const float* __restrict__ Dv,
    float* __restrict__ out, int N)
{
    constexpr int BM = 32;
    constexpr int ST = 4;
    constexpr int K  = DD;
    __shared__ float As[ST][BM * SA];
    __shared__ float Bs[ST][16 * SB];
    __shared__ float ps1[128], ps2[128];
    __shared__ float mu_s[BM], rs_s[BM];
    int tid = threadIdx.x;
    int warp = tid >> 5, lane = tid & 31;
    int m0 = blockIdx.y * BM, n0 = blockIdx.x * 64;

    int kk = (tid & 3) << 2;
    int a_r = tid >> 2;
    const float* Ap = A + (size_t)(m0 + a_r) * K + kk;
    int nb = (tid & 15) << 2;
    int kb = tid >> 4;
    const float* Wp = W + (size_t)kb * N + n0 + nb;

    constexpr int NIT = K / 16;   // 32

    auto issue = [&](int it) {
        int slot = it % ST;
        int k0 = it * 16;
        cp16(&As[slot][a_r * SA + kk],       Ap + k0);
        cp16(&Bs[slot][kb * SB + nb],        Wp + (size_t)k0 * N);
        cp16(&Bs[slot][(kb + 8) * SB + nb],  Wp + (size_t)(k0 + 8) * N);
        cp_commit();
    };

    issue(0); issue(1); issue(2);

    // row stats: 4 threads per row, 128 elements each
    {
        int row = tid >> 2, part = tid & 3;
        const float* rp = A + (size_t)(m0 + row) * K + part * 128;
        float s1 = 0.f, s2 = 0.f;
        #pragma unroll 8
        for (int i = 0; i < 32; i++) {
            float4 v = *(const float4*)(rp + i * 4);
            s1 += v.x + v.y + v.z + v.w;
            s2 += v.x * v.x + v.y * v.y + v.z * v.z + v.w * v.w;
        }
        ps1[tid] = s1; ps2[tid] = s2;
    }
    __syncthreads();
    if (tid < BM) {
        float a1 = ps1[tid * 4] + ps1[tid * 4 + 1] + ps1[tid * 4 + 2] + ps1[tid * 4 + 3];
        float a2 = ps2[tid * 4] + ps2[tid * 4 + 1] + ps2[tid * 4 + 2] + ps2[tid * 4 + 3];
        float mu = a1 * (1.f / K);
        float var = a2 * (1.f / K) - mu * mu;
        mu_s[tid] = mu;
        rs_s[tid] = rsqrtf(var + EPSV);
    }

    int warp_n = warp * 16;
    float c[2][2][4] = {};
    for (int it = 0; it < NIT; it++) {
        cp_wait<2>();
        __syncthreads();
        mma_tile32(As[it % ST], Bs[it % ST], warp_n, lane, c);
        if (it + ST - 1 < NIT) issue(it + ST - 1);
        else cp_commit();
    }

    int g = lane >> 2, tg = lane & 3;
    #pragma unroll
    for (int mt = 0; mt < 2; mt++) {
        #pragma unroll
        for (int nt = 0; nt < 2; nt++) {
            int cb = n0 + warp_n + nt * 8 + 2 * tg;
            float c0 = Cv[cb], c1v = Cv[cb + 1];
            float d0 = Dv[cb], d1v = Dv[cb + 1];
            #pragma unroll
            for (int h = 0; h < 2; h++) {
                int rl = mt * 16 + g + h * 8;
                int r  = m0 + rl;
                float mu = mu_s[rl], rs = rs_s[rl];
                float murs = mu * rs;
                float v0 = rs * c[mt][nt][2 * h]     + c0  - murs * d0;
                float v1 = rs * c[mt][nt][2 * h + 1] + c1v - murs * d1v;
                if (EPI == 1) {
                    v0 = 0.5f * v0 * (1.0f + erff(v0 * 0.70710678118654752f));
                    v1 = 0.5f * v1 * (1.0f + erff(v1 * 0.70710678118654752f));
                }
                *(float2*)&out[(size_t)r * N + cb] = make_float2(v0, v1);
            }
        }
    }
}

// ---------------- token LN + FiLM + spatial mean pool --------------------
__global__ __launch_bounds__(512) void pool_film_kernel(
    const float* __restrict__ z, const float* __restrict__ film_w,
    const float* __restrict__ film_b, const float* __restrict__ tokg,
    const float* __restrict__ tokb)
{
    int bt = blockIdx.x;
    int tid = threadIdx.x;
    int warp = tid >> 5, lane = tid & 31;
    __shared__ float mu_s[64], rs_s[64];
    __shared__ float zs[32];
    if (tid < 32) zs[tid] = z[bt * 32 + tid];

    const float* base = g_tok + (size_t)bt * NTOK * DD;
    for (int tt = 0; tt < 4; tt++) {
        int nn = warp * 4 + tt;
        const float* row = base + nn * DD;
        float s1 = 0.f, s2 = 0.f;
        for (int d = lane; d < DD; d += 32) { float v = row[d]; s1 += v; s2 += v * v; }
        #pragma unroll
        for (int off = 16; off; off >>= 1) {
            s1 += __shfl_xor_sync(0xffffffffu, s1, off);
            s2 += __shfl_xor_sync(0xffffffffu, s2, off);
        }
        if (lane == 0) {
            float mu  = s1 * (1.f / DD);
            float var = s2 * (1.f / DD) - mu * mu;
            mu_s[nn] = mu;
            rs_s[nn] = rsqrtf(var + EPSV);
        }
    }
    __syncthreads();
    int d = tid;
    float acc = 0.f;
    #pragma unroll 8
    for (int nn = 0; nn < NTOK; nn++)
        acc += (base[nn * DD + d] - mu_s[nn]) * rs_s[nn];
    float pooled = tokg[d] * (acc * (1.f / NTOK)) + tokb[d];
    float gamma = film_b[d], beta = film_b[DD + d];
    #pragma unroll
    for (int j = 0; j < 32; j++) {
        float zv = zs[j];
        gamma += zv * film_w[j * (2 * DD) + d];
        beta  += zv * film_w[j * (2 * DD) + DD + d];
    }
    g_h[bt * DD + d] = (1.f + 0.5f * gamma) * pooled + 0.5f * beta;
}

// ---------------- attention: one block per (batch, head) -----------------
__global__ __launch_bounds__(256) void attn_kernel()
{
    __shared__ float qs[32][64], ks[32][64], vs[32][64];
    __shared__ float sc[32][33];
    int blk = blockIdx.x;
    int b = blk >> 3, hh = blk & 7;
    int tid = threadIdx.x;

    for (int idx = tid; idx < 2048; idx += 256) {
        int t = idx >> 6, d = idx & 63;
        const float* p = g_kqv + (b * 32 + t) * (3 * DD) + hh * 64 + d;
        ks[t][d] = p[0];
        qs[t][d] = p[DD];
        vs[t][d] = p[2 * DD];
    }
    __syncthreads();
    for (int idx = tid; idx < 1024; idx += 256) {
        int t = idx >> 5, d0 = idx & 31;
        float sn = g_ropes[idx], cs = g_ropec[idx];
        float q0 = qs[t][d0], q1 = qs[t][d0 + 32];
        qs[t][d0]      = q0 * cs - q1 * sn;
        qs[t][d0 + 32] = q1 * cs + q0 * sn;
        float k0 = ks[t][d0], k1 = ks[t][d0 + 32];
        ks[t][d0]      = k0 * cs - k1 * sn;
        ks[t][d0 + 32] = k1 * cs + k0 * sn;
    }
    __syncthreads();
    for (int idx = tid; idx < 1024; idx += 256) {
        int tq = idx >> 5, tk = idx & 31;
        float s = -INFINITY;
        if (tk <= tq) {
            s = 0.f;
            #pragma unroll 16
            for (int d2 = 0; d2 < 64; d2++) s += qs[tq][d2] * ks[tk][d2];
            s *= 0.125f;
        }
        sc[tq][tk] = s;
    }
    __syncthreads();
    int warp = tid >> 5, lane = tid & 31;
    for (int i = 0; i < 4; i++) {
        int rw = warp + i * 8;
        float sv = sc[rw][lane];
        float mx = sv;
        #pragma unroll
        for (int off = 16; off; off >>= 1) mx = fmaxf(mx, __shfl_xor_sync(0xffffffffu, mx, off));
        float e = expf(sv - mx);
        float sum = e;
        #pragma unroll
        for (int off = 16; off; off >>= 1) sum += __shfl_xor_sync(0xffffffffu, sum, off);
        sc[rw][lane] = e / sum;
    }
    __syncthreads();
    for (int idx = tid; idx < 2048; idx += 256) {
        int tq = idx >> 6, d = idx & 63;
        float a = 0.f;
        for (int tk = 0; tk <= tq; tk++) a += sc[tq][tk] * vs[tk][d];
        g_yv[(b * 32 + tq) * DD + hh * 64 + d] = a;
    }
}

// ---------------- head: LN + dot ----------------------------------------
__global__ __launch_bounds__(256) void head_kernel(
    const float* __restrict__ g, const float* __restrict__ bb,
    const float* __restrict__ w, const float* __restrict__ bias,
    float* __restrict__ out)
{
    int row  = blockIdx.x * 8 + (threadIdx.x >> 5);
    int lane = threadIdx.x & 31;
    const float* r = g_h + row * DD;
    float v[16];
    float s1 = 0.f, s2 = 0.f;
    #pragma unroll
    for (int i = 0; i < 16; i++) {
        v[i] = r[lane + i * 32];
        s1 += v[i]; s2 += v[i] * v[i];
    }
    #pragma unroll
    for (int off = 16; off; off >>= 1) {
        s1 += __shfl_xor_sync(0xffffffffu, s1, off);
        s2 += __shfl_xor_sync(0xffffffffu, s2, off);
    }
    float mu   = s1 * (1.f / DD);
    float var  = s2 * (1.f / DD) - mu * mu;
    float rstd = rsqrtf(var + EPSV);
    float dot = 0.f;
    #pragma unroll
    for (int i = 0; i < 16; i++) {
        int d = lane + i * 32;
        float ln = (v[i] - mu) * rstd * g[d] + bb[d];
        dot += ln * w[d];
    }
    #pragma unroll
    for (int off = 16; off; off >>= 1) dot += __shfl_xor_sync(0xffffffffu, dot, off);
    if (lane == 0) out[row] = dot + bias[0];
}

// ---------------- launch ----------------
extern "C" void kernel_launch(void* const* d_in, const int* in_sizes, int n_in,
                              void* d_out, int out_size)
{
    const float* x        = (const float*)d_in[0];
    const float* z        = (const float*)d_in[1];
    const float* conv_w   = (const float*)d_in[2];
    const float* conv_b   = (const float*)d_in[3];
    const float* tok_g    = (const float*)d_in[4];
    const float* tok_b    = (const float*)d_in[5];
    const float* film_w   = (const float*)d_in[6];
    const float* film_b   = (const float*)d_in[7];
    const float* ln1_g    = (const float*)d_in[8];
    const float* ln1_b    = (const float*)d_in[9];
    const float* kqv_w    = (const float*)d_in[10];
    const float* kqv_b    = (const float*)d_in[11];
    const float* proj_w   = (const float*)d_in[12];
    const float* proj_b   = (const float*)d_in[13];
    const float* ln2_g    = (const float*)d_in[14];
    const float* ln2_b    = (const float*)d_in[15];
    const float* mlp_w1   = (const float*)d_in[16];
    const float* mlp_b1   = (const float*)d_in[17];
    const float* mlp_w2   = (const float*)d_in[18];
    const float* mlp_b2   = (const float*)d_in[19];
    const float* rs_attn  = (const float*)d_in[20];
    const float* rs_mlp   = (const float*)d_in[21];
    const float* head_g   = (const float*)d_in[22];
    const float* head_b   = (const float*)d_in[23];
    const float* head_w   = (const float*)d_in[24];
    const float* head_bia = (const float*)d_in[25];
    float* out = (float*)d_out;

    float *p_kqv, *p_yv, *p_mid, *p_h;
    float *p_w1s, *p_w2s, *p_c1, *p_d1, *p_c2, *p_d2;
    cudaGetSymbolAddress((void**)&p_kqv, g_kqv);
    cudaGetSymbolAddress((void**)&p_yv,  g_yv);
    cudaGetSymbolAddress((void**)&p_mid, g_mid);
    cudaGetSymbolAddress((void**)&p_h,   g_h);
    cudaGetSymbolAddress((void**)&p_w1s, g_w1s);
    cudaGetSymbolAddress((void**)&p_w2s, g_w2s);
    cudaGetSymbolAddress((void**)&p_c1,  g_c1);
    cudaGetSymbolAddress((void**)&p_d1,  g_d1);
    cudaGetSymbolAddress((void**)&p_c2,  g_c2);
    cudaGetSymbolAddress((void**)&p_d2,  g_d2);

    transpose_w_kernel<<<(DD * K_CONV + 255) / 256, 256>>>(conv_w);
    rope_kernel<<<1, 1024>>>();
    prep_lnw_kernel<<<dim3(6, LL), 256>>>(kqv_w, ln1_g, ln1_b, kqv_b,
                                          p_w1s, p_c1, p_d1, 3 * DD);
    prep_lnw_kernel<<<dim3(8, LL), 256>>>(mlp_w1, ln2_g, ln2_b, mlp_b1,
                                          p_w2s, p_c2, p_d2, 4 * DD);
    conv_gemm_tc<<<dim3(8, 256), 256>>>(x, conv_b);
    pool_film_kernel<<<BT, 512>>>(z, film_w, film_b, tok_g, tok_b);

    for (int i = 0; i < LL; i++) {
        gemm_lnw_tc<0><<<dim3(24, 16), 128>>>(p_h, p_w1s + (size_t)i * DD * 3 * DD,
                                              p_c1 + i * 3 * DD, p_d1 + i * 3 * DD,
                                              p_kqv, 3 * DD);
        attn_kernel<<<128, 256>>>();
        gemm_tc<2><<<dim3(8, 16), 128>>>(p_yv, proj_w + (size_t)i * DD * DD,
                                         proj_b + i * DD, p_h, rs_attn + i,
                                         p_h, BT, DD, DD);
        gemm_lnw_tc<1><<<dim3(32, 16), 128>>>(p_h, p_w2s + (size_t)i * DD * 4 * DD,
                                              p_c2 + i * 4 * DD, p_d2 + i * 4 * DD,
                                              p_mid, 4 * DD);
        gemm_tc<2><<<dim3(8, 16), 128>>>(p_mid, mlp_w2 + (size_t)i * 4 * DD * DD,
                                         mlp_b2 + i * DD, p_h, rs_mlp + i,
                                         p_h, BT, DD, 4 * DD);
    }
    head_kernel<<<64, 256>>>(head_g, head_b, head_w, head_bia, out);
}

// round 10
// speedup vs baseline: 1.1713x; 1.1713x over previous
#include <cuda_runtime.h>
#include <math.h>
#include <stdint.h>

// ---------------- problem constants ----------------
#define BB    16
#define TT    32
#define CC    3
#define HH    64
#define WW    64
#define DD    512
#define LL    6
#define BT    512          // B*T
#define NTOK  64           // tokens per frame (8x8)
#define M_CONV 32768       // B*T*NTOK
#define K_CONV 576         // C*KT*P*P
#define EPSV  1e-5f

#define SA    20           // As row stride (floats)
#define SB    72           // Bs row stride (floats)

// ---------------- scratch (device globals; no allocation) ----------------
__device__ float g_tok[M_CONV * DD];
__device__ float g_wT [K_CONV * DD];
__device__ float g_h  [BT * DD];
__device__ float g_xi [BT * DD];
__device__ float g_kqv[BT * 3 * DD];
__device__ float g_yv [BT * DD];
__device__ float g_mid[BT * 4 * DD];
__device__ float g_ropes[TT * 32];
__device__ float g_ropec[TT * 32];

// ---------------- helpers ----------------
__device__ __forceinline__ uint32_t f2tf(float f) {
    uint32_t u;
    asm("cvt.rna.tf32.f32 %0, %1;" : "=r"(u) : "f"(f));
    return u;
}

__device__ __forceinline__ void mma1688(float* c, const uint32_t* a, const uint32_t* b) {
    asm volatile(
        "mma.sync.aligned.m16n8k8.row.col.f32.tf32.tf32.f32 "
        "{%0,%1,%2,%3}, {%4,%5,%6,%7}, {%8,%9}, {%0,%1,%2,%3};"
        : "+f"(c[0]), "+f"(c[1]), "+f"(c[2]), "+f"(c[3])
        : "r"(a[0]), "r"(a[1]), "r"(a[2]), "r"(a[3]), "r"(b[0]), "r"(b[1]));
}

__device__ __forceinline__ void cp16(void* smem, const void* gmem) {
    uint32_t s = (uint32_t)__cvta_generic_to_shared(smem);
    asm volatile("cp.async.cg.shared.global [%0], [%1], 16;\n" :: "r"(s), "l"(gmem));
}
__device__ __forceinline__ void cp16z(void* smem, const void* gmem, bool pred) {
    uint32_t s = (uint32_t)__cvta_generic_to_shared(smem);
    int sz = pred ? 16 : 0;
    asm volatile("cp.async.cg.shared.global [%0], [%1], 16, %2;\n" :: "r"(s), "l"(gmem), "r"(sz));
}
__device__ __forceinline__ void cp_commit() {
    asm volatile("cp.async.commit_group;\n");
}
template<int N>
__device__ __forceinline__ void cp_wait() {
    asm volatile("cp.async.wait_group %0;\n" :: "n"(N));
}

// ---------------- weight transpose ----------------
__global__ void transpose_w_kernel(const float* __restrict__ w) {
    int idx = blockIdx.x * 256 + threadIdx.x;
    if (idx < DD * K_CONV) {
        int d = idx / K_CONV, k = idx - d * K_CONV;
        g_wT[k * DD + d] = w[idx];
    }
}

// ---------------- RoPE table ----------------
__global__ void rope_kernel() {
    int tid = threadIdx.x;          // 1024 threads
    int t = tid >> 5, d0 = tid & 31;
    float freq = exp2f(-(float)d0 * (13.287712379549449f / 32.f));
    float ang = (float)t * freq;
    float s, c;
    sincosf(ang, &s, &c);
    g_ropes[tid] = s;
    g_ropec[tid] = c;
}

// ---- warp tile 32x32 (2 m16 x 4 n8) for conv ----
__device__ __forceinline__ void mma_tile_f32(
    const float* As, const float* Bs, int warp_m, int warp_n, int lane, float c[2][4][4])
{
    int g  = lane >> 2;
    int tg = lane & 3;
    #pragma unroll
    for (int ks = 0; ks < 16; ks += 8) {
        uint32_t a[2][4], b[4][2];
        #pragma unroll
        for (int mt = 0; mt < 2; mt++) {
            int r0 = warp_m + mt * 16 + g;
            a[mt][0] = f2tf(As[(r0    ) * SA + ks + tg    ]);
            a[mt][1] = f2tf(As[(r0 + 8) * SA + ks + tg    ]);
            a[mt][2] = f2tf(As[(r0    ) * SA + ks + tg + 4]);
            a[mt][3] = f2tf(As[(r0 + 8) * SA + ks + tg + 4]);
        }
        #pragma unroll
        for (int nt = 0; nt < 4; nt++) {
            int col = warp_n + nt * 8 + g;
            b[nt][0] = f2tf(Bs[(ks + tg    ) * SB + col]);
            b[nt][1] = f2tf(Bs[(ks + tg + 4) * SB + col]);
        }
        #pragma unroll
        for (int mt = 0; mt < 2; mt++)
            #pragma unroll
            for (int nt = 0; nt < 4; nt++)
                mma1688(c[mt][nt], a[mt], b[nt]);
    }
}

// ---- warp tile 32x16 (2 m16 x 2 n8) for transformer GEMMs ----
__device__ __forceinline__ void mma_tile32(
    const float* As, const float* Bs, int warp_n, int lane, float c[2][2][4])
{
    int g  = lane >> 2;
    int tg = lane & 3;
    #pragma unroll
    for (int ks = 0; ks < 16; ks += 8) {
        uint32_t a[2][4], b[2][2];
        #pragma unroll
        for (int mt = 0; mt < 2; mt++) {
            int r0 = mt * 16 + g;
            a[mt][0] = f2tf(As[(r0    ) * SA + ks + tg    ]);
            a[mt][1] = f2tf(As[(r0 + 8) * SA + ks + tg    ]);
            a[mt][2] = f2tf(As[(r0    ) * SA + ks + tg + 4]);
            a[mt][3] = f2tf(As[(r0 + 8) * SA + ks + tg + 4]);
        }
        #pragma unroll
        for (int nt = 0; nt < 2; nt++) {
            int col = warp_n + nt * 8 + g;
            b[nt][0] = f2tf(Bs[(ks + tg    ) * SB + col]);
            b[nt][1] = f2tf(Bs[(ks + tg + 4) * SB + col]);
        }
        #pragma unroll
        for (int mt = 0; mt < 2; mt++)
            #pragma unroll
            for (int nt = 0; nt < 2; nt++)
                mma1688(c[mt][nt], a[mt], b[nt]);
    }
}

// ---------------- conv as GEMM (im2col, tf32 TC, 3-stage cp.async) --------
__global__ __launch_bounds__(256) void conv_gemm_tc(
    const float* __restrict__ x, const float* __restrict__ bias)
{
    constexpr int BM = 128;
    constexpr int ST = 3;
    __shared__ float As[ST][BM * SA];
    __shared__ float Bs[ST][16 * SB];
    int tid = threadIdx.x;
    int warp = tid >> 5, lane = tid & 31;
    int m0 = blockIdx.y * BM, n0 = blockIdx.x * 64;

    int kk = (tid & 3) << 2;
    const float* xb[2];
    int trow[2], arow[2];
    #pragma unroll
    for (int p = 0; p < 2; p++) {
        int row = p * 64 + (tid >> 2);
        arow[p] = row;
        int m = m0 + row;
        int b = m >> 11;
        int t = (m >> 6) & 31;
        int n = m & 63;
        int hn = n >> 3, wn = n & 7;
        xb[p]  = x + b * (TT * CC * HH * WW) + (hn * 8) * WW + wn * 8;
        trow[p] = t;
    }

    int nb = (tid & 15) << 2;
    int kb = tid >> 4;
    const float* Wp = g_wT + kb * DD + n0 + nb;

    constexpr int NIT = K_CONV / 16;

    auto issue = [&](int it) {
        int slot = it % ST;
        float* as = As[slot];
        float* bs = Bs[slot];
        int kg  = it * 16 + kk;
        int cch = kg / 192;
        int r   = kg - cch * 192;
        int dt  = r >> 6;
        int pix = r & 63;
        int ph  = pix >> 3, pw = pix & 7;
        #pragma unroll
        for (int p = 0; p < 2; p++) {
            int tin = trow[p] + dt - 2;
            bool ok = (tin >= 0);
            const float* src = xb[p] + (ok ? tin : 0) * (CC * HH * WW) + cch * (HH * WW) + ph * WW + pw;
            cp16z(&as[arow[p] * SA + kk], src, ok);
        }
        cp16(&bs[kb * SB + nb], Wp + (size_t)(it * 16) * DD);
        cp_commit();
    };

    issue(0); issue(1);

    int warp_m = (warp >> 1) * 32, warp_n = (warp & 1) * 32;
    float c[2][4][4] = {};
    for (int it = 0; it < NIT; it++) {
        cp_wait<1>();
        __syncthreads();
        mma_tile_f32(As[it % ST], Bs[it % ST], warp_m, warp_n, lane, c);
        if (it + ST - 1 < NIT) issue(it + ST - 1);
        else cp_commit();
    }

    int g = lane >> 2, tg = lane & 3;
    #pragma unroll
    for (int mt = 0; mt < 2; mt++) {
        #pragma unroll
        for (int nt = 0; nt < 4; nt++) {
            int cb = n0 + warp_n + nt * 8 + 2 * tg;
            float b0 = bias[cb], b1 = bias[cb + 1];
            int r0 = m0 + warp_m + mt * 16 + g;
            *(float2*)&g_tok[(size_t)r0 * DD + cb]       = make_float2(c[mt][nt][0] + b0, c[mt][nt][1] + b1);
            *(float2*)&g_tok[(size_t)(r0 + 8) * DD + cb] = make_float2(c[mt][nt][2] + b0, c[mt][nt][3] + b1);
        }
    }
}

// ---------------- transformer GEMM: BM=32, BN=64, 128 thr, 4-stage -------
// EPI 0: out = A@W + bias ; EPI 1: gelu(.) ; EPI 2: res + (*scale_p)*(.)
template<int EPI>
__global__ __launch_bounds__(128) void gemm_tc(
    const float* __restrict__ A, const float* __restrict__ W,
    const float* __restrict__ bias, const float* __restrict__ res,
    const float* __restrict__ scale_p, float* __restrict__ out,
    int M, int N, int K)
{
    constexpr int BM = 32;
    constexpr int ST = 4;
    __shared__ float As[ST][BM * SA];
    __shared__ float Bs[ST][16 * SB];
    int tid = threadIdx.x;
    int warp = tid >> 5, lane = tid & 31;
    int m0 = blockIdx.y * BM, n0 = blockIdx.x * 64;

    int kk = (tid & 3) << 2;
    int a_r = tid >> 2;
    const float* Ap = A + (size_t)(m0 + a_r) * K + kk;
    int nb = (tid & 15) << 2;
    int kb = tid >> 4;
    const float* Wp = W + (size_t)kb * N + n0 + nb;

    int NIT = K / 16;

    auto issue = [&](int it) {
        int slot = it % ST;
        int k0 = it * 16;
        cp16(&As[slot][a_r * SA + kk],       Ap + k0);
        cp16(&Bs[slot][kb * SB + nb],        Wp + (size_t)k0 * N);
        cp16(&Bs[slot][(kb + 8) * SB + nb],  Wp + (size_t)(k0 + 8) * N);
        cp_commit();
    };

    issue(0); issue(1); issue(2);

    int warp_n = warp * 16;
    float c[2][2][4] = {};
    for (int it = 0; it < NIT; it++) {
        cp_wait<2>();
        __syncthreads();
        mma_tile32(As[it % ST], Bs[it % ST], warp_n, lane, c);
        if (it + ST - 1 < NIT) issue(it + ST - 1);
        else cp_commit();
    }

    float s = (EPI == 2) ? *scale_p : 0.f;
    int g = lane >> 2, tg = lane & 3;
    #pragma unroll
    for (int mt = 0; mt < 2; mt++) {
        #pragma unroll
        for (int nt = 0; nt < 2; nt++) {
            int cb = n0 + warp_n + nt * 8 + 2 * tg;
            float b0 = bias[cb], b1 = bias[cb + 1];
            #pragma unroll
            for (int h = 0; h < 2; h++) {
                int r = m0 + mt * 16 + g + h * 8;
                float v0 = c[mt][nt][2 * h]     + b0;
                float v1 = c[mt][nt][2 * h + 1] + b1;
                if (EPI == 1) {
                    v0 = 0.5f * v0 * (1.0f + erff(v0 * 0.70710678118654752f));
                    v1 = 0.5f * v1 * (1.0f + erff(v1 * 0.70710678118654752f));
                }
                if (EPI == 2) {
                    v0 = res[(size_t)r * N + cb]     + s * v0;
                    v1 = res[(size_t)r * N + cb + 1] + s * v1;
                }
                *(float2*)&out[(size_t)r * N + cb] = make_float2(v0, v1);
            }
        }
    }
}

// ---------------- token LN + FiLM + spatial mean pool (single pass) ------
// Token tile staged in dynamic smem: g_tok read once.
extern __shared__ float tok_s[];   // NTOK * DD floats = 128 KB
__global__ __launch_bounds__(512) void pool_film_kernel(
    const float* __restrict__ z, const float* __restrict__ film_w,
    const float* __restrict__ film_b, const float* __restrict__ tokg,
    const float* __restrict__ tokb)
{
    int bt = blockIdx.x;
    int tid = threadIdx.x;
    int warp = tid >> 5, lane = tid & 31;
    __shared__ float mu_s[64], rs_s[64];
    __shared__ float zs[32];
    if (tid < 32) zs[tid] = z[bt * 32 + tid];

    const float* base = g_tok + (size_t)bt * NTOK * DD;
    // stage tile (coalesced, float4)
    #pragma unroll 4
    for (int i = tid; i < NTOK * DD / 4; i += 512)
        *(float4*)&tok_s[i * 4] = *(const float4*)&base[i * 4];
    __syncthreads();

    // per-token stats: warp per token, 4 tokens per warp
    for (int tt = 0; tt < 4; tt++) {
        int nn = warp * 4 + tt;
        const float* row = tok_s + nn * DD;
        float s1 = 0.f, s2 = 0.f;
        #pragma unroll
        for (int i = 0; i < 16; i++) {
            float v = row[lane + i * 32];
            s1 += v; s2 += v * v;
        }
        #pragma unroll
        for (int off = 16; off; off >>= 1) {
            s1 += __shfl_xor_sync(0xffffffffu, s1, off);
            s2 += __shfl_xor_sync(0xffffffffu, s2, off);
        }
        if (lane == 0) {
            float mu  = s1 * (1.f / DD);
            float var = s2 * (1.f / DD) - mu * mu;
            mu_s[nn] = mu;
            rs_s[nn] = rsqrtf(var + EPSV);
        }
    }
    __syncthreads();
    // per-channel accumulation
    int d = tid;
    float acc = 0.f;
    #pragma unroll 8
    for (int nn = 0; nn < NTOK; nn++)
        acc += (tok_s[nn * DD + d] - mu_s[nn]) * rs_s[nn];
    float pooled = tokg[d] * (acc * (1.f / NTOK)) + tokb[d];
    float gamma = film_b[d], beta = film_b[DD + d];
    #pragma unroll
    for (int j = 0; j < 32; j++) {
        float zv = zs[j];
        gamma += zv * film_w[j * (2 * DD) + d];
        beta  += zv * film_w[j * (2 * DD) + DD + d];
    }
    g_h[bt * DD + d] = (1.f + 0.5f * gamma) * pooled + 0.5f * beta;
}

// ---------------- row LayerNorm (warp per row, 128 blocks) ---------------
__global__ __launch_bounds__(128) void ln_kernel(
    const float* __restrict__ in, const float* __restrict__ g,
    const float* __restrict__ b, float* __restrict__ out)
{
    int row  = blockIdx.x * 4 + (threadIdx.x >> 5);
    int lane = threadIdx.x & 31;
    const float* r = in + row * DD;
    float v[16];
    float s1 = 0.f, s2 = 0.f;
    #pragma unroll
    for (int i = 0; i < 16; i++) {
        v[i] = r[lane + i * 32];
        s1 += v[i]; s2 += v[i] * v[i];
    }
    #pragma unroll
    for (int off = 16; off; off >>= 1) {
        s1 += __shfl_xor_sync(0xffffffffu, s1, off);
        s2 += __shfl_xor_sync(0xffffffffu, s2, off);
    }
    float mu  = s1 * (1.f / DD);
    float var = s2 * (1.f / DD) - mu * mu;
    float rstd = rsqrtf(var + EPSV);
    #pragma unroll
    for (int i = 0; i < 16; i++) {
        int d = lane + i * 32;
        out[row * DD + d] = (v[i] - mu) * rstd * g[d] + b[d];
    }
}

// ---------------- attention: one block per (batch, head) -----------------
__global__ __launch_bounds__(256) void attn_kernel()
{
    __shared__ float qs[32][64], ks[32][64], vs[32][64];
    __shared__ float sc[32][33];
    int blk = blockIdx.x;
    int b = blk >> 3, hh = blk & 7;
    int tid = threadIdx.x;

    for (int idx = tid; idx < 2048; idx += 256) {
        int t = idx >> 6, d = idx & 63;
        const float* p = g_kqv + (b * 32 + t) * (3 * DD) + hh * 64 + d;
        ks[t][d] = p[0];
        qs[t][d] = p[DD];
        vs[t][d] = p[2 * DD];
    }
    __syncthreads();
    for (int idx = tid; idx < 1024; idx += 256) {
        int t = idx >> 5, d0 = idx & 31;
        float sn = g_ropes[idx], cs = g_ropec[idx];
        float q0 = qs[t][d0], q1 = qs[t][d0 + 32];
        qs[t][d0]      = q0 * cs - q1 * sn;
        qs[t][d0 + 32] = q1 * cs + q0 * sn;
        float k0 = ks[t][d0], k1 = ks[t][d0 + 32];
        ks[t][d0]      = k0 * cs - k1 * sn;
        ks[t][d0 + 32] = k1 * cs + k0 * sn;
    }
    __syncthreads();
    for (int idx = tid; idx < 1024; idx += 256) {
        int tq = idx >> 5, tk = idx & 31;
        float s = -INFINITY;
        if (tk <= tq) {
            s = 0.f;
            #pragma unroll 16
            for (int d2 = 0; d2 < 64; d2++) s += qs[tq][d2] * ks[tk][d2];
            s *= 0.125f;
        }
        sc[tq][tk] = s;
    }
    __syncthreads();
    int warp = tid >> 5, lane = tid & 31;
    for (int i = 0; i < 4; i++) {
        int rw = warp + i * 8;
        float sv = sc[rw][lane];
        float mx = sv;
        #pragma unroll
        for (int off = 16; off; off >>= 1) mx = fmaxf(mx, __shfl_xor_sync(0xffffffffu, mx, off));
        float e = expf(sv - mx);
        float sum = e;
        #pragma unroll
        for (int off = 16; off; off >>= 1) sum += __shfl_xor_sync(0xffffffffu, sum, off);
        sc[rw][lane] = e / sum;
    }
    __syncthreads();
    for (int idx = tid; idx < 2048; idx += 256) {
        int tq = idx >> 6, d = idx & 63;
        float a = 0.f;
        for (int tk = 0; tk <= tq; tk++) a += sc[tq][tk] * vs[tk][d];
        g_yv[(b * 32 + tq) * DD + hh * 64 + d] = a;
    }
}

// ---------------- head: LN + dot ----------------------------------------
__global__ __launch_bounds__(256) void head_kernel(
    const float* __restrict__ g, const float* __restrict__ bb,
    const float* __restrict__ w, const float* __restrict__ bias,
    float* __restrict__ out)
{
    int row  = blockIdx.x * 8 + (threadIdx.x >> 5);
    int lane = threadIdx.x & 31;
    const float* r = g_h + row * DD;
    float v[16];
    float s1 = 0.f, s2 = 0.f;
    #pragma unroll
    for (int i = 0; i < 16; i++) {
        v[i] = r[lane + i * 32];
        s1 += v[i]; s2 += v[i] * v[i];
    }
    #pragma unroll
    for (int off = 16; off; off >>= 1) {
        s1 += __shfl_xor_sync(0xffffffffu, s1, off);
        s2 += __shfl_xor_sync(0xffffffffu, s2, off);
    }
    float mu   = s1 * (1.f / DD);
    float var  = s2 * (1.f / DD) - mu * mu;
    float rstd = rsqrtf(var + EPSV);
    float dot = 0.f;
    #pragma unroll
    for (int i = 0; i < 16; i++) {
        int d = lane + i * 32;
        float ln = (v[i] - mu) * rstd * g[d] + bb[d];
        dot += ln * w[d];
    }
    #pragma unroll
    for (int off = 16; off; off >>= 1) dot += __shfl_xor_sync(0xffffffffu, dot, off);
    if (lane == 0) out[row] = dot + bias[0];
}

// ---------------- launch ----------------
extern "C" void kernel_launch(void* const* d_in, const int* in_sizes, int n_in,
                              void* d_out, int out_size)
{
    const float* x        = (const float*)d_in[0];
    const float* z        = (const float*)d_in[1];
    const float* conv_w   = (const float*)d_in[2];
    const float* conv_b   = (const float*)d_in[3];
    const float* tok_g    = (const float*)d_in[4];
    const float* tok_b    = (const float*)d_in[5];
    const float* film_w   = (const float*)d_in[6];
    const float* film_b   = (const float*)d_in[7];
    const float* ln1_g    = (const float*)d_in[8];
    const float* ln1_b    = (const float*)d_in[9];
    const float* kqv_w    = (const float*)d_in[10];
    const float* kqv_b    = (const float*)d_in[11];
    const float* proj_w   = (const float*)d_in[12];
    const float* proj_b   = (const float*)d_in[13];
    const float* ln2_g    = (const float*)d_in[14];
    const float* ln2_b    = (const float*)d_in[15];
    const float* mlp_w1   = (const float*)d_in[16];
    const float* mlp_b1   = (const float*)d_in[17];
    const float* mlp_w2   = (const float*)d_in[18];
    const float* mlp_b2   = (const float*)d_in[19];
    const float* rs_attn  = (const float*)d_in[20];
    const float* rs_mlp   = (const float*)d_in[21];
    const float* head_g   = (const float*)d_in[22];
    const float* head_b   = (const float*)d_in[23];
    const float* head_w   = (const float*)d_in[24];
    const float* head_bia = (const float*)d_in[25];
    float* out = (float*)d_out;

    float *p_xi, *p_kqv, *p_yv, *p_mid, *p_h;
    cudaGetSymbolAddress((void**)&p_xi,  g_xi);
    cudaGetSymbolAddress((void**)&p_kqv, g_kqv);
    cudaGetSymbolAddress((void**)&p_yv,  g_yv);
    cudaGetSymbolAddress((void**)&p_mid, g_mid);
    cudaGetSymbolAddress((void**)&p_h,   g_h);

    static int smem_set = 0;
    if (!smem_set) {
        cudaFuncSetAttribute(pool_film_kernel,
                             cudaFuncAttributeMaxDynamicSharedMemorySize,
                             NTOK * DD * (int)sizeof(float));
        smem_set = 1;
    }

    transpose_w_kernel<<<(DD * K_CONV + 255) / 256, 256>>>(conv_w);
    rope_kernel<<<1, 1024>>>();
    conv_gemm_tc<<<dim3(8, 256), 256>>>(x, conv_b);
    pool_film_kernel<<<BT, 512, NTOK * DD * sizeof(float)>>>(z, film_w, film_b, tok_g, tok_b);

    for (int i = 0; i < LL; i++) {
        ln_kernel<<<128, 128>>>(p_h, ln1_g + i * DD, ln1_b + i * DD, p_xi);
        gemm_tc<0><<<dim3(24, 16), 128>>>(p_xi, kqv_w + (size_t)i * DD * 3 * DD,
                                          kqv_b + i * 3 * DD, nullptr, nullptr,
                                          p_kqv, BT, 3 * DD, DD);
        attn_kernel<<<128, 256>>>();
        gemm_tc<2><<<dim3(8, 16), 128>>>(p_yv, proj_w + (size_t)i * DD * DD,
                                         proj_b + i * DD, p_h, rs_attn + i,
                                         p_h, BT, DD, DD);
        ln_kernel<<<128, 128>>>(p_h, ln2_g + i * DD, ln2_b + i * DD, p_xi);
        gemm_tc<1><<<dim3(32, 16), 128>>>(p_xi, mlp_w1 + (size_t)i * DD * 4 * DD,
                                          mlp_b1 + i * 4 * DD, nullptr, nullptr,
                                          p_mid, BT, 4 * DD, DD);
        gemm_tc<2><<<dim3(8, 16), 128>>>(p_mid, mlp_w2 + (size_t)i * 4 * DD * DD,
                                         mlp_b2 + i * DD, p_h, rs_mlp + i,
                                         p_h, BT, DD, 4 * DD);
    }
    head_kernel<<<64, 256>>>(head_g, head_b, head_w, head_bia, out);
}

// round 12
// speedup vs baseline: 1.2500x; 1.0672x over previous
#include <cuda_runtime.h>
#include <math.h>
#include <stdint.h>

// ---------------- problem constants ----------------
#define BB    16
#define TT    32
#define CC    3
#define HH    64
#define WW    64
#define DD    512
#define LL    6
#define BT    512          // B*T
#define NTOK  64           // tokens per frame (8x8)
#define M_CONV 32768       // B*T*NTOK
#define K_CONV 576         // C*KT*P*P
#define EPSV  1e-5f

#define SA    20           // As row stride (floats)
#define SB    72           // Bs row stride (floats)

// ---------------- scratch (device globals; no allocation) ----------------
__device__ float g_tok[M_CONV * DD];
__device__ float g_wT [K_CONV * DD];     // transposed conv weight, tf32-pre-rounded
__device__ float g_h  [BT * DD];
__device__ float g_xi [BT * DD];         // LN output, tf32-pre-rounded
__device__ float g_kqv[BT * 3 * DD];     // full fp32 (feeds attention math)
__device__ float g_yv [BT * DD];         // attn output, tf32-pre-rounded
__device__ float g_mid[BT * 4 * DD];     // gelu output, tf32-pre-rounded
__device__ float g_ropes[TT * 32];
__device__ float g_ropec[TT * 32];

// ---------------- helpers ----------------
__device__ __forceinline__ uint32_t f2tf(float f) {
    uint32_t u;
    asm("cvt.rna.tf32.f32 %0, %1;" : "=r"(u) : "f"(f));
    return u;
}
__device__ __forceinline__ float f2tf_f(float f) {
    return __uint_as_float(f2tf(f));
}

__device__ __forceinline__ void mma1688(float* c, const uint32_t* a, const uint32_t* b) {
    asm volatile(
        "mma.sync.aligned.m16n8k8.row.col.f32.tf32.tf32.f32 "
        "{%0,%1,%2,%3}, {%4,%5,%6,%7}, {%8,%9}, {%0,%1,%2,%3};"
        : "+f"(c[0]), "+f"(c[1]), "+f"(c[2]), "+f"(c[3])
        : "r"(a[0]), "r"(a[1]), "r"(a[2]), "r"(a[3]), "r"(b[0]), "r"(b[1]));
}

__device__ __forceinline__ void cp16(void* smem, const void* gmem) {
    uint32_t s = (uint32_t)__cvta_generic_to_shared(smem);
    asm volatile("cp.async.cg.shared.global [%0], [%1], 16;\n" :: "r"(s), "l"(gmem));
}
__device__ __forceinline__ void cp16z(void* smem, const void* gmem, bool pred) {
    uint32_t s = (uint32_t)__cvta_generic_to_shared(smem);
    int sz = pred ? 16 : 0;
    asm volatile("cp.async.cg.shared.global [%0], [%1], 16, %2;\n" :: "r"(s), "l"(gmem), "r"(sz));
}
__device__ __forceinline__ void cp_commit() {
    asm volatile("cp.async.commit_group;\n");
}
template<int N>
__device__ __forceinline__ void cp_wait() {
    asm volatile("cp.async.wait_group %0;\n" :: "n"(N));
}

// ---------------- weight transpose (+ tf32 pre-round) ----------------
__global__ void transpose_w_kernel(const float* __restrict__ w) {
    int idx = blockIdx.x * 256 + threadIdx.x;
    if (idx < DD * K_CONV) {
        int d = idx / K_CONV, k = idx - d * K_CONV;
        g_wT[k * DD + d] = f2tf_f(w[idx]);
    }
}

// ---------------- RoPE table ----------------
__global__ void rope_kernel() {
    int tid = threadIdx.x;          // 1024 threads
    int t = tid >> 5, d0 = tid & 31;
    float freq = exp2f(-(float)d0 * (13.287712379549449f / 32.f));
    float ang = (float)t * freq;
    float s, c;
    sincosf(ang, &s, &c);
    g_ropes[tid] = s;
    g_ropec[tid] = c;
}

// ---- conv warp tile 32x32 (2 m16 x 4 n8): A needs cvt, B pre-rounded ----
__device__ __forceinline__ void mma_tile_conv(
    const float* As, const float* Bs, int warp_m, int warp_n, int lane, float c[2][4][4])
{
    int g  = lane >> 2;
    int tg = lane & 3;
    const uint32_t* Bu = (const uint32_t*)Bs;
    #pragma unroll
    for (int ks = 0; ks < 16; ks += 8) {
        uint32_t a[2][4], b[4][2];
        #pragma unroll
        for (int mt = 0; mt < 2; mt++) {
            int r0 = warp_m + mt * 16 + g;
            a[mt][0] = f2tf(As[(r0    ) * SA + ks + tg    ]);
            a[mt][1] = f2tf(As[(r0 + 8) * SA + ks + tg    ]);
            a[mt][2] = f2tf(As[(r0    ) * SA + ks + tg + 4]);
            a[mt][3] = f2tf(As[(r0 + 8) * SA + ks + tg + 4]);
        }
        #pragma unroll
        for (int nt = 0; nt < 4; nt++) {
            int col = warp_n + nt * 8 + g;
            b[nt][0] = Bu[(ks + tg    ) * SB + col];
            b[nt][1] = Bu[(ks + tg + 4) * SB + col];
        }
        #pragma unroll
        for (int mt = 0; mt < 2; mt++)
            #pragma unroll
            for (int nt = 0; nt < 4; nt++)
                mma1688(c[mt][nt], a[mt], b[nt]);
    }
}

// ---- transformer warp tile 32x16: A pre-rounded (plain load), B needs cvt --
__device__ __forceinline__ void mma_tile32(
    const float* As, const float* Bs, int warp_n, int lane, float c[2][2][4])
{
    int g  = lane >> 2;
    int tg = lane & 3;
    const uint32_t* Au = (const uint32_t*)As;
    #pragma unroll
    for (int ks = 0; ks < 16; ks += 8) {
        uint32_t a[2][4], b[2][2];
        #pragma unroll
        for (int mt = 0; mt < 2; mt++) {
            int r0 = mt * 16 + g;
            a[mt][0] = Au[(r0    ) * SA + ks + tg    ];
            a[mt][1] = Au[(r0 + 8) * SA + ks + tg    ];
            a[mt][2] = Au[(r0    ) * SA + ks + tg + 4];
            a[mt][3] = Au[(r0 + 8) * SA + ks + tg + 4];
        }
        #pragma unroll
        for (int nt = 0; nt < 2; nt++) {
            int col = warp_n + nt * 8 + g;
            b[nt][0] = f2tf(Bs[(ks + tg    ) * SB + col]);
            b[nt][1] = f2tf(Bs[(ks + tg + 4) * SB + col]);
        }
        #pragma unroll
        for (int mt = 0; mt < 2; mt++)
            #pragma unroll
            for (int nt = 0; nt < 2; nt++)
                mma1688(c[mt][nt], a[mt], b[nt]);
    }
}

// ---------------- conv as GEMM (im2col, tf32 TC, 3-stage cp.async) --------
__global__ __launch_bounds__(256) void conv_gemm_tc(
    const float* __restrict__ x, const float* __restrict__ bias)
{
    constexpr int BM = 128;
    constexpr int ST = 3;
    __shared__ float As[ST][BM * SA];
    __shared__ float Bs[ST][16 * SB];
    int tid = threadIdx.x;
    int warp = tid >> 5, lane = tid & 31;
    int m0 = blockIdx.y * BM, n0 = blockIdx.x * 64;

    int kk = (tid & 3) << 2;
    const float* xb[2];
    int trow[2], arow[2];
    #pragma unroll
    for (int p = 0; p < 2; p++) {
        int row = p * 64 + (tid >> 2);
        arow[p] = row;
        int m = m0 + row;
        int b = m >> 11;
        int t = (m >> 6) & 31;
        int n = m & 63;
        int hn = n >> 3, wn = n & 7;
        xb[p]  = x + b * (TT * CC * HH * WW) + (hn * 8) * WW + wn * 8;
        trow[p] = t;
    }

    int nb = (tid & 15) << 2;
    int kb = tid >> 4;
    const float* Wp = g_wT + kb * DD + n0 + nb;

    constexpr int NIT = K_CONV / 16;

    auto issue = [&](int it) {
        int slot = it % ST;
        float* as = As[slot];
        float* bs = Bs[slot];
        int kg  = it * 16 + kk;
        int cch = kg / 192;
        int r   = kg - cch * 192;
        int dt  = r >> 6;
        int pix = r & 63;
        int ph  = pix >> 3, pw = pix & 7;
        #pragma unroll
        for (int p = 0; p < 2; p++) {
            int tin = trow[p] + dt - 2;
            bool ok = (tin >= 0);
            const float* src = xb[p] + (ok ? tin : 0) * (CC * HH * WW) + cch * (HH * WW) + ph * WW + pw;
            cp16z(&as[arow[p] * SA + kk], src, ok);
        }
        cp16(&bs[kb * SB + nb], Wp + (size_t)(it * 16) * DD);
        cp_commit();
    };

    issue(0); issue(1);

    int warp_m = (warp >> 1) * 32, warp_n = (warp & 1) * 32;
    float c[2][4][4] = {};
    for (int it = 0; it < NIT; it++) {
        cp_wait<1>();
        __syncthreads();
        mma_tile_conv(As[it % ST], Bs[it % ST], warp_m, warp_n, lane, c);
        if (it + ST - 1 < NIT) issue(it + ST - 1);
        else cp_commit();
    }

    int g = lane >> 2, tg = lane & 3;
    #pragma unroll
    for (int mt = 0; mt < 2; mt++) {
        #pragma unroll
        for (int nt = 0; nt < 4; nt++) {
            int cb = n0 + warp_n + nt * 8 + 2 * tg;
            float b0 = bias[cb], b1 = bias[cb + 1];
            int r0 = m0 + warp_m + mt * 16 + g;
            *(float2*)&g_tok[(size_t)r0 * DD + cb]       = make_float2(c[mt][nt][0] + b0, c[mt][nt][1] + b1);
            *(float2*)&g_tok[(size_t)(r0 + 8) * DD + cb] = make_float2(c[mt][nt][2] + b0, c[mt][nt][3] + b1);
        }
    }
}

// ---------------- transformer GEMM: BM=32, BN=64, 128 thr, 4-stage -------
// EPI 0: out = A@W + bias         (full fp32 out; feeds attention)
// EPI 1: out = tf32(gelu(A@W+b))  (feeds mlp2 A-path)
// EPI 2: out = res + (*scale_p)*(A@W + bias)   (residual, fp32)
template<int EPI>
__global__ __launch_bounds__(128) void gemm_tc(
    const float* __restrict__ A, const float* __restrict__ W,
    const float* __restrict__ bias, const float* __restrict__ res,
    const float* __restrict__ scale_p, float* __restrict__ out,
    int M, int N, int K)
{
    constexpr int BM = 32;
    constexpr int ST = 4;
    __shared__ float As[ST][BM * SA];
    __shared__ float Bs[ST][16 * SB];
    int tid = threadIdx.x;
    int warp = tid >> 5, lane = tid & 31;
    int m0 = blockIdx.y * BM, n0 = blockIdx.x * 64;

    int kk = (tid & 3) << 2;
    int a_r = tid >> 2;
    const float* Ap = A + (size_t)(m0 + a_r) * K + kk;
    int nb = (tid & 15) << 2;
    int kb = tid >> 4;
    const float* Wp = W + (size_t)kb * N + n0 + nb;

    int NIT = K / 16;

    auto issue = [&](int it) {
        int slot = it % ST;
        int k0 = it * 16;
        cp16(&As[slot][a_r * SA + kk],       Ap + k0);
        cp16(&Bs[slot][kb * SB + nb],        Wp + (size_t)k0 * N);
        cp16(&Bs[slot][(kb + 8) * SB + nb],  Wp + (size_t)(k0 + 8) * N);
        cp_commit();
    };

    issue(0); issue(1); issue(2);

    int warp_n = warp * 16;
    float c[2][2][4] = {};
    for (int it = 0; it < NIT; it++) {
        cp_wait<2>();
        __syncthreads();
        mma_tile32(As[it % ST], Bs[it % ST], warp_n, lane, c);
        if (it + ST - 1 < NIT) issue(it + ST - 1);
        else cp_commit();
    }

    float s = (EPI == 2) ? *scale_p : 0.f;
    int g = lane >> 2, tg = lane & 3;
    #pragma unroll
    for (int mt = 0; mt < 2; mt++) {
        #pragma unroll
        for (int nt = 0; nt < 2; nt++) {
            int cb = n0 + warp_n + nt * 8 + 2 * tg;
            float b0 = bias[cb], b1 = bias[cb + 1];
            #pragma unroll
            for (int h = 0; h < 2; h++) {
                int r = m0 + mt * 16 + g + h * 8;
                float v0 = c[mt][nt][2 * h]     + b0;
                float v1 = c[mt][nt][2 * h + 1] + b1;
                if (EPI == 1) {
                    v0 = 0.5f * v0 * (1.0f + erff(v0 * 0.70710678118654752f));
                    v1 = 0.5f * v1 * (1.0f + erff(v1 * 0.70710678118654752f));
                    v0 = f2tf_f(v0);   // pre-round for mlp2 A fragments
                    v1 = f2tf_f(v1);
                }
                if (EPI == 2) {
                    v0 = res[(size_t)r * N + cb]     + s * v0;
                    v1 = res[(size_t)r * N + cb + 1] + s * v1;
                }
                *(float2*)&out[(size_t)r * N + cb] = make_float2(v0, v1);
            }
        }
    }
}

// ---------------- token LN + FiLM + spatial mean pool (two-pass) ---------
__global__ __launch_bounds__(512) void pool_film_kernel(
    const float* __restrict__ z, const float* __restrict__ film_w,
    const float* __restrict__ film_b, const float* __restrict__ tokg,
    const float* __restrict__ tokb)
{
    int bt = blockIdx.x;
    int tid = threadIdx.x;
    int warp = tid >> 5, lane = tid & 31;
    __shared__ float mu_s[64], rs_s[64];
    __shared__ float zs[32];
    if (tid < 32) zs[tid] = z[bt * 32 + tid];

    const float* base = g_tok + (size_t)bt * NTOK * DD;
    for (int tt = 0; tt < 4; tt++) {
        int nn = warp * 4 + tt;
        const float* row = base + nn * DD;
        float s1 = 0.f, s2 = 0.f;
        for (int d = lane; d < DD; d += 32) { float v = row[d]; s1 += v; s2 += v * v; }
        #pragma unroll
        for (int off = 16; off; off >>= 1) {
            s1 += __shfl_xor_sync(0xffffffffu, s1, off);
            s2 += __shfl_xor_sync(0xffffffffu, s2, off);
        }
        if (lane == 0) {
            float mu  = s1 * (1.f / DD);
            float var = s2 * (1.f / DD) - mu * mu;
            mu_s[nn] = mu;
            rs_s[nn] = rsqrtf(var + EPSV);
        }
    }
    __syncthreads();
    int d = tid;
    float acc = 0.f;
    #pragma unroll 8
    for (int nn = 0; nn < NTOK; nn++)
        acc += (base[nn * DD + d] - mu_s[nn]) * rs_s[nn];
    float pooled = tokg[d] * (acc * (1.f / NTOK)) + tokb[d];
    float gamma = film_b[d], beta = film_b[DD + d];
    #pragma unroll
    for (int j = 0; j < 32; j++) {
        float zv = zs[j];
        gamma += zv * film_w[j * (2 * DD) + d];
        beta  += zv * film_w[j * (2 * DD) + DD + d];
    }
    g_h[bt * DD + d] = (1.f + 0.5f * gamma) * pooled + 0.5f * beta;
}

// ---------------- row LayerNorm (pre-rounded output) ---------------------
__global__ __launch_bounds__(128) void ln_kernel(
    const float* __restrict__ in, const float* __restrict__ g,
    const float* __restrict__ b, float* __restrict__ out)
{
    int row  = blockIdx.x * 4 + (threadIdx.x >> 5);
    int lane = threadIdx.x & 31;
    const float* r = in + row * DD;
    float v[16];
    float s1 = 0.f, s2 = 0.f;
    #pragma unroll
    for (int i = 0; i < 16; i++) {
        v[i] = r[lane + i * 32];
        s1 += v[i]; s2 += v[i] * v[i];
    }
    #pragma unroll
    for (int off = 16; off; off >>= 1) {
        s1 += __shfl_xor_sync(0xffffffffu, s1, off);
        s2 += __shfl_xor_sync(0xffffffffu, s2, off);
    }
    float mu  = s1 * (1.f / DD);
    float var = s2 * (1.f / DD) - mu * mu;
    float rstd = rsqrtf(var + EPSV);
    #pragma unroll
    for (int i = 0; i < 16; i++) {
        int d = lane + i * 32;
        out[row * DD + d] = f2tf_f((v[i] - mu) * rstd * g[d] + b[d]);
    }
}

// ---------------- attention: one block per (batch, head) -----------------
__global__ __launch_bounds__(256) void attn_kernel()
{
    __shared__ float qs[32][64], ks[32][64], vs[32][64];
    __shared__ float sc[32][33];
    int blk = blockIdx.x;
    int b = blk >> 3, hh = blk & 7;
    int tid = threadIdx.x;

    for (int idx = tid; idx < 2048; idx += 256) {
        int t = idx >> 6, d = idx & 63;
        const float* p = g_kqv + (b * 32 + t) * (3 * DD) + hh * 64 + d;
        ks[t][d] = p[0];
        qs[t][d] = p[DD];
        vs[t][d] = p[2 * DD];
    }
    __syncthreads();
    for (int idx = tid; idx < 1024; idx += 256) {
        int t = idx >> 5, d0 = idx & 31;
        float sn = g_ropes[idx], cs = g_ropec[idx];
        float q0 = qs[t][d0], q1 = qs[t][d0 + 32];
        qs[t][d0]      = q0 * cs - q1 * sn;
        qs[t][d0 + 32] = q1 * cs + q0 * sn;
        float k0 = ks[t][d0], k1 = ks[t][d0 + 32];
        ks[t][d0]      = k0 * cs - k1 * sn;
        ks[t][d0 + 32] = k1 * cs + k0 * sn;
    }
    __syncthreads();
    for (int idx = tid; idx < 1024; idx += 256) {
        int tq = idx >> 5, tk = idx & 31;
        float s = -INFINITY;
        if (tk <= tq) {
            s = 0.f;
            #pragma unroll 16
            for (int d2 = 0; d2 < 64; d2++) s += qs[tq][d2] * ks[tk][d2];
            s *= 0.125f;
        }
        sc[tq][tk] = s;
    }
    __syncthreads();
    int warp = tid >> 5, lane = tid & 31;
    for (int i = 0; i < 4; i++) {
        int rw = warp + i * 8;
        float sv = sc[rw][lane];
        float mx = sv;
        #pragma unroll
        for (int off = 16; off; off >>= 1) mx = fmaxf(mx, __shfl_xor_sync(0xffffffffu, mx, off));
        float e = expf(sv - mx);
        float sum = e;
        #pragma unroll
        for (int off = 16; off; off >>= 1) sum += __shfl_xor_sync(0xffffffffu, sum, off);
        sc[rw][lane] = e / sum;
    }
    __syncthreads();
    for (int idx = tid; idx < 2048; idx += 256) {
        int tq = idx >> 6, d = idx & 63;
        float a = 0.f;
        for (int tk = 0; tk <= tq; tk++) a += sc[tq][tk] * vs[tk][d];
        g_yv[(b * 32 + tq) * DD + hh * 64 + d] = f2tf_f(a);   // pre-round for proj
    }
}

// ---------------- head: LN + dot ----------------------------------------
__global__ __launch_bounds__(256) void head_kernel(
    const float* __restrict__ g, const float* __restrict__ bb,
    const float* __restrict__ w, const float* __restrict__ bias,
    float* __restrict__ out)
{
    int row  = blockIdx.x * 8 + (threadIdx.x >> 5);
    int lane = threadIdx.x & 31;
    const float* r = g_h + row * DD;
    float v[16];
    float s1 = 0.f, s2 = 0.f;
    #pragma unroll
    for (int i = 0; i < 16; i++) {
        v[i] = r[lane + i * 32];
        s1 += v[i]; s2 += v[i] * v[i];
    }
    #pragma unroll
    for (int off = 16; off; off >>= 1) {
        s1 += __shfl_xor_sync(0xffffffffu, s1, off);
        s2 += __shfl_xor_sync(0xffffffffu, s2, off);
    }
    float mu   = s1 * (1.f / DD);
    float var  = s2 * (1.f / DD) - mu * mu;
    float rstd = rsqrtf(var + EPSV);
    float dot = 0.f;
    #pragma unroll
    for (int i = 0; i < 16; i++) {
        int d = lane + i * 32;
        float ln = (v[i] - mu) * rstd * g[d] + bb[d];
        dot += ln * w[d];
    }
    #pragma unroll
    for (int off = 16; off; off >>= 1) dot += __shfl_xor_sync(0xffffffffu, dot, off);
    if (lane == 0) out[row] = dot + bias[0];
}

// ---------------- launch ----------------
extern "C" void kernel_launch(void* const* d_in, const int* in_sizes, int n_in,
                              void* d_out, int out_size)
{
    const float* x        = (const float*)d_in[0];
    const float* z        = (const float*)d_in[1];
    const float* conv_w   = (const float*)d_in[2];
    const float* conv_b   = (const float*)d_in[3];
    const float* tok_g    = (const float*)d_in[4];
    const float* tok_b    = (const float*)d_in[5];
    const float* film_w   = (const float*)d_in[6];
    const float* film_b   = (const float*)d_in[7];
    const float* ln1_g    = (const float*)d_in[8];
    const float* ln1_b    = (const float*)d_in[9];
    const float* kqv_w    = (const float*)d_in[10];
    const float* kqv_b    = (const float*)d_in[11];
    const float* proj_w   = (const float*)d_in[12];
    const float* proj_b   = (const float*)d_in[13];
    const float* ln2_g    = (const float*)d_in[14];
    const float* ln2_b    = (const float*)d_in[15];
    const float* mlp_w1   = (const float*)d_in[16];
    const float* mlp_b1   = (const float*)d_in[17];
    const float* mlp_w2   = (const float*)d_in[18];
    const float* mlp_b2   = (const float*)d_in[19];
    const float* rs_attn  = (const float*)d_in[20];
    const float* rs_mlp   = (const float*)d_in[21];
    const float* head_g   = (const float*)d_in[22];
    const float* head_b   = (const float*)d_in[23];
    const float* head_w   = (const float*)d_in[24];
    const float* head_bia = (const float*)d_in[25];
    float* out = (float*)d_out;

    float *p_xi, *p_kqv, *p_yv, *p_mid, *p_h;
    cudaGetSymbolAddress((void**)&p_xi,  g_xi);
    cudaGetSymbolAddress((void**)&p_kqv, g_kqv);
    cudaGetSymbolAddress((void**)&p_yv,  g_yv);
    cudaGetSymbolAddress((void**)&p_mid, g_mid);
    cudaGetSymbolAddress((void**)&p_h,   g_h);

    transpose_w_kernel<<<(DD * K_CONV + 255) / 256, 256>>>(conv_w);
    rope_kernel<<<1, 1024>>>();
    conv_gemm_tc<<<dim3(8, 256), 256>>>(x, conv_b);
    pool_film_kernel<<<BT, 512>>>(z, film_w, film_b, tok_g, tok_b);

    for (int i = 0; i < LL; i++) {
        ln_kernel<<<128, 128>>>(p_h, ln1_g + i * DD, ln1_b + i * DD, p_xi);
        gemm_tc<0><<<dim3(24, 16), 128>>>(p_xi, kqv_w + (size_t)i * DD * 3 * DD,
                                          kqv_b + i * 3 * DD, nullptr, nullptr,
                                          p_kqv, BT, 3 * DD, DD);
        attn_kernel<<<128, 256>>>();
        gemm_tc<2><<<dim3(8, 16), 128>>>(p_yv, proj_w + (size_t)i * DD * DD,
                                         proj_b + i * DD, p_h, rs_attn + i,
                                         p_h, BT, DD, DD);
        ln_kernel<<<128, 128>>>(p_h, ln2_g + i * DD, ln2_b + i * DD, p_xi);
        gemm_tc<1><<<dim3(32, 16), 128>>>(p_xi, mlp_w1 + (size_t)i * DD * 4 * DD,
                                          mlp_b1 + i * 4 * DD, nullptr, nullptr,
                                          p_mid, BT, 4 * DD, DD);
        gemm_tc<2><<<dim3(8, 16), 128>>>(p_mid, mlp_w2 + (size_t)i * 4 * DD * DD,
                                         mlp_b2 + i * DD, p_h, rs_mlp + i,
                                         p_h, BT, DD, 4 * DD);
    }
    head_kernel<<<64, 256>>>(head_g, head_b, head_w, head_bia, out);
}

// round 13
// speedup vs baseline: 1.2600x; 1.0080x over previous
#include <cuda_runtime.h>
#include <math.h>
#include <stdint.h>

// ---------------- problem constants ----------------
#define BB    16
#define TT    32
#define CC    3
#define HH    64
#define WW    64
#define DD    512
#define LL    6
#define BT    512          // B*T
#define NTOK  64           // tokens per frame (8x8)
#define M_CONV 32768       // B*T*NTOK
#define K_CONV 576         // C*KT*P*P
#define EPSV  1e-5f

#define SA    20           // As row stride (floats)
#define SB    72           // Bs row stride (floats)
#define SB2   200          // fused-kernel Bs row stride (192 cols + pad)
#define SKV   193          // fused attn kqv row stride (conflict-free)

// ---------------- scratch (device globals; no allocation) ----------------
__device__ float g_tok[M_CONV * DD];
__device__ float g_wT [K_CONV * DD];     // transposed conv weight, tf32-pre-rounded
__device__ float g_h  [BT * DD];
__device__ float g_xi [BT * DD];         // LN output, tf32-pre-rounded
__device__ float g_yv [BT * DD];         // attn output, tf32-pre-rounded
__device__ float g_mid[BT * 4 * DD];     // gelu output, tf32-pre-rounded
__device__ float g_ropes[TT * 32];
__device__ float g_ropec[TT * 32];

// ---------------- helpers ----------------
__device__ __forceinline__ uint32_t f2tf(float f) {
    uint32_t u;
    asm("cvt.rna.tf32.f32 %0, %1;" : "=r"(u) : "f"(f));
    return u;
}
__device__ __forceinline__ float f2tf_f(float f) {
    return __uint_as_float(f2tf(f));
}

__device__ __forceinline__ void mma1688(float* c, const uint32_t* a, const uint32_t* b) {
    asm volatile(
        "mma.sync.aligned.m16n8k8.row.col.f32.tf32.tf32.f32 "
        "{%0,%1,%2,%3}, {%4,%5,%6,%7}, {%8,%9}, {%0,%1,%2,%3};"
        : "+f"(c[0]), "+f"(c[1]), "+f"(c[2]), "+f"(c[3])
        : "r"(a[0]), "r"(a[1]), "r"(a[2]), "r"(a[3]), "r"(b[0]), "r"(b[1]));
}

__device__ __forceinline__ void cp16(void* smem, const void* gmem) {
    uint32_t s = (uint32_t)__cvta_generic_to_shared(smem);
    asm volatile("cp.async.cg.shared.global [%0], [%1], 16;\n" :: "r"(s), "l"(gmem));
}
__device__ __forceinline__ void cp16z(void* smem, const void* gmem, bool pred) {
    uint32_t s = (uint32_t)__cvta_generic_to_shared(smem);
    int sz = pred ? 16 : 0;
    asm volatile("cp.async.cg.shared.global [%0], [%1], 16, %2;\n" :: "r"(s), "l"(gmem), "r"(sz));
}
__device__ __forceinline__ void cp_commit() {
    asm volatile("cp.async.commit_group;\n");
}
template<int N>
__device__ __forceinline__ void cp_wait() {
    asm volatile("cp.async.wait_group %0;\n" :: "n"(N));
}

// ---------------- weight transpose (+ tf32 pre-round) ----------------
__global__ void transpose_w_kernel(const float* __restrict__ w) {
    int idx = blockIdx.x * 256 + threadIdx.x;
    if (idx < DD * K_CONV) {
        int d = idx / K_CONV, k = idx - d * K_CONV;
        g_wT[k * DD + d] = f2tf_f(w[idx]);
    }
}

// ---------------- RoPE table ----------------
__global__ void rope_kernel() {
    int tid = threadIdx.x;          // 1024 threads
    int t = tid >> 5, d0 = tid & 31;
    float freq = exp2f(-(float)d0 * (13.287712379549449f / 32.f));
    float ang = (float)t * freq;
    float s, c;
    sincosf(ang, &s, &c);
    g_ropes[tid] = s;
    g_ropec[tid] = c;
}

// ---- conv warp tile 32x32 (2 m16 x 4 n8): A needs cvt, B pre-rounded ----
__device__ __forceinline__ void mma_tile_conv(
    const float* As, const float* Bs, int warp_m, int warp_n, int lane, float c[2][4][4])
{
    int g  = lane >> 2;
    int tg = lane & 3;
    const uint32_t* Bu = (const uint32_t*)Bs;
    #pragma unroll
    for (int ks = 0; ks < 16; ks += 8) {
        uint32_t a[2][4], b[4][2];
        #pragma unroll
        for (int mt = 0; mt < 2; mt++) {
            int r0 = warp_m + mt * 16 + g;
            a[mt][0] = f2tf(As[(r0    ) * SA + ks + tg    ]);
            a[mt][1] = f2tf(As[(r0 + 8) * SA + ks + tg    ]);
            a[mt][2] = f2tf(As[(r0    ) * SA + ks + tg + 4]);
            a[mt][3] = f2tf(As[(r0 + 8) * SA + ks + tg + 4]);
        }
        #pragma unroll
        for (int nt = 0; nt < 4; nt++) {
            int col = warp_n + nt * 8 + g;
            b[nt][0] = Bu[(ks + tg    ) * SB + col];
            b[nt][1] = Bu[(ks + tg + 4) * SB + col];
        }
        #pragma unroll
        for (int mt = 0; mt < 2; mt++)
            #pragma unroll
            for (int nt = 0; nt < 4; nt++)
                mma1688(c[mt][nt], a[mt], b[nt]);
    }
}

// ---- transformer warp tile 32x16: A pre-rounded (plain load), B needs cvt --
__device__ __forceinline__ void mma_tile32(
    const float* As, const float* Bs, int warp_n, int lane, float c[2][2][4])
{
    int g  = lane >> 2;
    int tg = lane & 3;
    const uint32_t* Au = (const uint32_t*)As;
    #pragma unroll
    for (int ks = 0; ks < 16; ks += 8) {
        uint32_t a[2][4], b[2][2];
        #pragma unroll
        for (int mt = 0; mt < 2; mt++) {
            int r0 = mt * 16 + g;
            a[mt][0] = Au[(r0    ) * SA + ks + tg    ];
            a[mt][1] = Au[(r0 + 8) * SA + ks + tg    ];
            a[mt][2] = Au[(r0    ) * SA + ks + tg + 4];
            a[mt][3] = Au[(r0 + 8) * SA + ks + tg + 4];
        }
        #pragma unroll
        for (int nt = 0; nt < 2; nt++) {
            int col = warp_n + nt * 8 + g;
            b[nt][0] = f2tf(Bs[(ks + tg    ) * SB + col]);
            b[nt][1] = f2tf(Bs[(ks + tg + 4) * SB + col]);
        }
        #pragma unroll
        for (int mt = 0; mt < 2; mt++)
            #pragma unroll
            for (int nt = 0; nt < 2; nt++)
                mma1688(c[mt][nt], a[mt], b[nt]);
    }
}

// ---------------- conv as GEMM (im2col, tf32 TC, 3-stage cp.async) --------
__global__ __launch_bounds__(256) void conv_gemm_tc(
    const float* __restrict__ x, const float* __restrict__ bias)
{
    constexpr int BM = 128;
    constexpr int ST = 3;
    __shared__ float As[ST][BM * SA];
    __shared__ float Bs[ST][16 * SB];
    int tid = threadIdx.x;
    int warp = tid >> 5, lane = tid & 31;
    int m0 = blockIdx.y * BM, n0 = blockIdx.x * 64;

    int kk = (tid & 3) << 2;
    const float* xb[2];
    int trow[2], arow[2];
    #pragma unroll
    for (int p = 0; p < 2; p++) {
        int row = p * 64 + (tid >> 2);
        arow[p] = row;
        int m = m0 + row;
        int b = m >> 11;
        int t = (m >> 6) & 31;
        int n = m & 63;
        int hn = n >> 3, wn = n & 7;
        xb[p]  = x + b * (TT * CC * HH * WW) + (hn * 8) * WW + wn * 8;
        trow[p] = t;
    }

    int nb = (tid & 15) << 2;
    int kb = tid >> 4;
    const float* Wp = g_wT + kb * DD + n0 + nb;

    constexpr int NIT = K_CONV / 16;

    auto issue = [&](int it) {
        int slot = it % ST;
        float* as = As[slot];
        float* bs = Bs[slot];
        int kg  = it * 16 + kk;
        int cch = kg / 192;
        int r   = kg - cch * 192;
        int dt  = r >> 6;
        int pix = r & 63;
        int ph  = pix >> 3, pw = pix & 7;
        #pragma unroll
        for (int p = 0; p < 2; p++) {
            int tin = trow[p] + dt - 2;
            bool ok = (tin >= 0);
            const float* src = xb[p] + (ok ? tin : 0) * (CC * HH * WW) + cch * (HH * WW) + ph * WW + pw;
            cp16z(&as[arow[p] * SA + kk], src, ok);
        }
        cp16(&bs[kb * SB + nb], Wp + (size_t)(it * 16) * DD);
        cp_commit();
    };

    issue(0); issue(1);

    int warp_m = (warp >> 1) * 32, warp_n = (warp & 1) * 32;
    float c[2][4][4] = {};
    for (int it = 0; it < NIT; it++) {
        cp_wait<1>();
        __syncthreads();
        mma_tile_conv(As[it % ST], Bs[it % ST], warp_m, warp_n, lane, c);
        if (it + ST - 1 < NIT) issue(it + ST - 1);
        else cp_commit();
    }

    int g = lane >> 2, tg = lane & 3;
    #pragma unroll
    for (int mt = 0; mt < 2; mt++) {
        #pragma unroll
        for (int nt = 0; nt < 4; nt++) {
            int cb = n0 + warp_n + nt * 8 + 2 * tg;
            float b0 = bias[cb], b1 = bias[cb + 1];
            int r0 = m0 + warp_m + mt * 16 + g;
            *(float2*)&g_tok[(size_t)r0 * DD + cb]       = make_float2(c[mt][nt][0] + b0, c[mt][nt][1] + b1);
            *(float2*)&g_tok[(size_t)(r0 + 8) * DD + cb] = make_float2(c[mt][nt][2] + b0, c[mt][nt][3] + b1);
        }
    }
}

// ---------------- transformer GEMM: BM=32, BN=64, 128 thr, 4-stage -------
// EPI 1: out = tf32(gelu(A@W+b))  (feeds mlp2 A-path)
// EPI 2: out = res + (*scale_p)*(A@W + bias)   (residual, fp32)
template<int EPI>
__global__ __launch_bounds__(128) void gemm_tc(
    const float* __restrict__ A, const float* __restrict__ W,
    const float* __restrict__ bias, const float* __restrict__ res,
    const float* __restrict__ scale_p, float* __restrict__ out,
    int M, int N, int K)
{
    constexpr int BM = 32;
    constexpr int ST = 4;
    __shared__ float As[ST][BM * SA];
    __shared__ float Bs[ST][16 * SB];
    int tid = threadIdx.x;
    int warp = tid >> 5, lane = tid & 31;
    int m0 = blockIdx.y * BM, n0 = blockIdx.x * 64;

    int kk = (tid & 3) << 2;
    int a_r = tid >> 2;
    const float* Ap = A + (size_t)(m0 + a_r) * K + kk;
    int nb = (tid & 15) << 2;
    int kb = tid >> 4;
    const float* Wp = W + (size_t)kb * N + n0 + nb;

    int NIT = K / 16;

    auto issue = [&](int it) {
        int slot = it % ST;
        int k0 = it * 16;
        cp16(&As[slot][a_r * SA + kk],       Ap + k0);
        cp16(&Bs[slot][kb * SB + nb],        Wp + (size_t)k0 * N);
        cp16(&Bs[slot][(kb + 8) * SB + nb],  Wp + (size_t)(k0 + 8) * N);
        cp_commit();
    };

    issue(0); issue(1); issue(2);

    int warp_n = warp * 16;
    float c[2][2][4] = {};
    for (int it = 0; it < NIT; it++) {
        cp_wait<2>();
        __syncthreads();
        mma_tile32(As[it % ST], Bs[it % ST], warp_n, lane, c);
        if (it + ST - 1 < NIT) issue(it + ST - 1);
        else cp_commit();
    }

    float s = (EPI == 2) ? *scale_p : 0.f;
    int g = lane >> 2, tg = lane & 3;
    #pragma unroll
    for (int mt = 0; mt < 2; mt++) {
        #pragma unroll
        for (int nt = 0; nt < 2; nt++) {
            int cb = n0 + warp_n + nt * 8 + 2 * tg;
            float b0 = bias[cb], b1 = bias[cb + 1];
            #pragma unroll
            for (int h = 0; h < 2; h++) {
                int r = m0 + mt * 16 + g + h * 8;
                float v0 = c[mt][nt][2 * h]     + b0;
                float v1 = c[mt][nt][2 * h + 1] + b1;
                if (EPI == 1) {
                    v0 = 0.5f * v0 * (1.0f + erff(v0 * 0.70710678118654752f));
                    v1 = 0.5f * v1 * (1.0f + erff(v1 * 0.70710678118654752f));
                    v0 = f2tf_f(v0);
                    v1 = f2tf_f(v1);
                }
                if (EPI == 2) {
                    v0 = res[(size_t)r * N + cb]     + s * v0;
                    v1 = res[(size_t)r * N + cb + 1] + s * v1;
                }
                *(float2*)&out[(size_t)r * N + cb] = make_float2(v0, v1);
            }
        }
    }
}

// ============ fused kqv GEMM + RoPE + attention ============
// block = (head, batch). A = g_xi rows [batch*32, +32), pre-rounded tf32.
// B = kqv_w columns {k,q,v} strips for this head (64 cols each at h*64, 512+h*64, 1024+h*64).
// After GEMM: RoPE on k,q; causal softmax; PV; write g_yv (tf32-rounded).
union FusedSmem {
    struct { float As[3][32 * SA]; float Bs[3][16 * SB2]; } mm;
    struct { float kqv[32][SKV];   float sc[32][33]; } at;
};

__global__ __launch_bounds__(128) void kqv_attn_kernel(
    const float* __restrict__ W,     // kqv_w layer base [512][1536]
    const float* __restrict__ bias)  // kqv_b layer base [1536]
{
    __shared__ FusedSmem u;
    int tid = threadIdx.x;
    int warp = tid >> 5, lane = tid & 31;
    int head = blockIdx.x, batch = blockIdx.y;
    int m0 = batch * 32;

    int kk  = (tid & 3) << 2;
    int a_r = tid >> 2;                      // 0..31
    const float* Ap = g_xi + (size_t)(m0 + a_r) * DD + kk;
    int brow = tid >> 4;                     // 0..7
    int bq   = (tid & 15) << 2;              // 0..60
    const float* Wb = W + head * 64 + bq;

    constexpr int ST = 3;
    constexpr int NIT = DD / 16;             // 32

    auto issue = [&](int it) {
        int slot = it % ST;
        int k0 = it * 16;
        cp16(&u.mm.As[slot][a_r * SA + kk], Ap + k0);
        #pragma unroll
        for (int p = 0; p < 3; p++) {
            const float* src = Wb + (size_t)(k0 + brow) * 1536 + p * 512;
            cp16(&u.mm.Bs[slot][brow * SB2 + p * 64 + bq],       src);
            cp16(&u.mm.Bs[slot][(brow + 8) * SB2 + p * 64 + bq], src + (size_t)8 * 1536);
        }
        cp_commit();
    };

    issue(0); issue(1);

    int g  = lane >> 2;
    int tg = lane & 3;
    int warp_n = warp * 48;
    float c[2][6][4] = {};
    for (int it = 0; it < NIT; it++) {
        cp_wait<1>();
        __syncthreads();
        const float* As = u.mm.As[it % ST];
        const float* Bs = u.mm.Bs[it % ST];
        const uint32_t* Au = (const uint32_t*)As;
        #pragma unroll
        for (int ks = 0; ks < 16; ks += 8) {
            uint32_t a[2][4], b[6][2];
            #pragma unroll
            for (int mt = 0; mt < 2; mt++) {
                int r0 = mt * 16 + g;
                a[mt][0] = Au[(r0    ) * SA + ks + tg    ];
                a[mt][1] = Au[(r0 + 8) * SA + ks + tg    ];
                a[mt][2] = Au[(r0    ) * SA + ks + tg + 4];
                a[mt][3] = Au[(r0 + 8) * SA + ks + tg + 4];
            }
            #pragma unroll
            for (int nt = 0; nt < 6; nt++) {
                int col = warp_n + nt * 8 + g;
                b[nt][0] = f2tf(Bs[(ks + tg    ) * SB2 + col]);
                b[nt][1] = f2tf(Bs[(ks + tg + 4) * SB2 + col]);
            }
            #pragma unroll
            for (int mt = 0; mt < 2; mt++)
                #pragma unroll
                for (int nt = 0; nt < 6; nt++)
                    mma1688(c[mt][nt], a[mt], b[nt]);
        }
        if (it + ST - 1 < NIT) issue(it + ST - 1);
        else cp_commit();
    }

    // ---- epilogue: accumulators (+bias) -> at.kqv smem ----
    __syncthreads();     // all MMA smem reads done; safe to alias
    #pragma unroll
    for (int mt = 0; mt < 2; mt++) {
        #pragma unroll
        for (int nt = 0; nt < 6; nt++) {
            int col = warp_n + nt * 8 + 2 * tg;
            int p = col >> 6;
            int cbase = p * 512 + head * 64 + (col & 63);
            float b0 = bias[cbase], b1 = bias[cbase + 1];
            int r0 = mt * 16 + g;
            u.at.kqv[r0][col]         = c[mt][nt][0] + b0;
            u.at.kqv[r0][col + 1]     = c[mt][nt][1] + b1;
            u.at.kqv[r0 + 8][col]     = c[mt][nt][2] + b0;
            u.at.kqv[r0 + 8][col + 1] = c[mt][nt][3] + b1;
        }
    }
    __syncthreads();

    // ---- RoPE on k (cols 0..63) and q (cols 64..127), in place ----
    #pragma unroll
    for (int i = 0; i < 8; i++) {
        int idx = tid + i * 128;           // 1024
        int t = idx >> 5, d0 = idx & 31;
        float sn = g_ropes[idx], cs = g_ropec[idx];
        float k0 = u.at.kqv[t][d0],      k1 = u.at.kqv[t][d0 + 32];
        u.at.kqv[t][d0]      = k0 * cs - k1 * sn;
        u.at.kqv[t][d0 + 32] = k1 * cs + k0 * sn;
        float q0 = u.at.kqv[t][64 + d0], q1 = u.at.kqv[t][64 + d0 + 32];
        u.at.kqv[t][64 + d0]      = q0 * cs - q1 * sn;
        u.at.kqv[t][64 + d0 + 32] = q1 * cs + q0 * sn;
    }
    __syncthreads();

    // ---- scores (causal) ----
    #pragma unroll
    for (int i = 0; i < 8; i++) {
        int idx = tid + i * 128;           // 1024
        int tq = idx >> 5, tk = idx & 31;
        float s = -INFINITY;
        if (tk <= tq) {
            s = 0.f;
            #pragma unroll 16
            for (int d2 = 0; d2 < 64; d2++)
                s += u.at.kqv[tq][64 + d2] * u.at.kqv[tk][d2];
            s *= 0.125f;
        }
        u.at.sc[tq][tk] = s;
    }
    __syncthreads();

    // ---- softmax: warp per row, 8 rows per warp ----
    #pragma unroll
    for (int i = 0; i < 8; i++) {
        int rw = warp * 8 + i;
        float sv = u.at.sc[rw][lane];
        float mx = sv;
        #pragma unroll
        for (int off = 16; off; off >>= 1) mx = fmaxf(mx, __shfl_xor_sync(0xffffffffu, mx, off));
        float e = expf(sv - mx);
        float sum = e;
        #pragma unroll
        for (int off = 16; off; off >>= 1) sum += __shfl_xor_sync(0xffffffffu, sum, off);
        u.at.sc[rw][lane] = e / sum;
    }
    __syncthreads();

    // ---- out = P @ V ----
    #pragma unroll
    for (int i = 0; i < 16; i++) {
        int idx = tid + i * 128;           // 2048
        int tq = idx >> 6, d = idx & 63;
        float a = 0.f;
        for (int tk = 0; tk <= tq; tk++)
            a += u.at.sc[tq][tk] * u.at.kqv[tk][128 + d];
        g_yv[(size_t)(m0 + tq) * DD + head * 64 + d] = f2tf_f(a);
    }
}

// ---------------- token LN + FiLM + spatial mean pool (two-pass) ---------
__global__ __launch_bounds__(512) void pool_film_kernel(
    const float* __restrict__ z, const float* __restrict__ film_w,
    const float* __restrict__ film_b, const float* __restrict__ tokg,
    const float* __restrict__ tokb)
{
    int bt = blockIdx.x;
    int tid = threadIdx.x;
    int warp = tid >> 5, lane = tid & 31;
    __shared__ float mu_s[64], rs_s[64];
    __shared__ float zs[32];
    if (tid < 32) zs[tid] = z[bt * 32 + tid];

    const float* base = g_tok + (size_t)bt * NTOK * DD;
    for (int tt = 0; tt < 4; tt++) {
        int nn = warp * 4 + tt;
        const float* row = base + nn * DD;
        float s1 = 0.f, s2 = 0.f;
        for (int d = lane; d < DD; d += 32) { float v = row[d]; s1 += v; s2 += v * v; }
        #pragma unroll
        for (int off = 16; off; off >>= 1) {
            s1 += __shfl_xor_sync(0xffffffffu, s1, off);
            s2 += __shfl_xor_sync(0xffffffffu, s2, off);
        }
        if (lane == 0) {
            float mu  = s1 * (1.f / DD);
            float var = s2 * (1.f / DD) - mu * mu;
            mu_s[nn] = mu;
            rs_s[nn] = rsqrtf(var + EPSV);
        }
    }
    __syncthreads();
    int d = tid;
    float acc = 0.f;
    #pragma unroll 8
    for (int nn = 0; nn < NTOK; nn++)
        acc += (base[nn * DD + d] - mu_s[nn]) * rs_s[nn];
    float pooled = tokg[d] * (acc * (1.f / NTOK)) + tokb[d];
    float gamma = film_b[d], beta = film_b[DD + d];
    #pragma unroll
    for (int j = 0; j < 32; j++) {
        float zv = zs[j];
        gamma += zv * film_w[j * (2 * DD) + d];
        beta  += zv * film_w[j * (2 * DD) + DD + d];
    }
    g_h[bt * DD + d] = (1.f + 0.5f * gamma) * pooled + 0.5f * beta;
}

// ---------------- row LayerNorm (pre-rounded output) ---------------------
__global__ __launch_bounds__(128) void ln_kernel(
    const float* __restrict__ in, const float* __restrict__ g,
    const float* __restrict__ b, float* __restrict__ out)
{
    int row  = blockIdx.x * 4 + (threadIdx.x >> 5);
    int lane = threadIdx.x & 31;
    const float* r = in + row * DD;
    float v[16];
    float s1 = 0.f, s2 = 0.f;
    #pragma unroll
    for (int i = 0; i < 16; i++) {
        v[i] = r[lane + i * 32];
        s1 += v[i]; s2 += v[i] * v[i];
    }
    #pragma unroll
    for (int off = 16; off; off >>= 1) {
        s1 += __shfl_xor_sync(0xffffffffu, s1, off);
        s2 += __shfl_xor_sync(0xffffffffu, s2, off);
    }
    float mu  = s1 * (1.f / DD);
    float var = s2 * (1.f / DD) - mu * mu;
    float rstd = rsqrtf(var + EPSV);
    #pragma unroll
    for (int i = 0; i < 16; i++) {
        int d = lane + i * 32;
        out[row * DD + d] = f2tf_f((v[i] - mu) * rstd * g[d] + b[d]);
    }
}

// ---------------- head: LN + dot ----------------------------------------
__global__ __launch_bounds__(256) void head_kernel(
    const float* __restrict__ g, const float* __restrict__ bb,
    const float* __restrict__ w, const float* __restrict__ bias,
    float* __restrict__ out)
{
    int row  = blockIdx.x * 8 + (threadIdx.x >> 5);
    int lane = threadIdx.x & 31;
    const float* r = g_h + row * DD;
    float v[16];
    float s1 = 0.f, s2 = 0.f;
    #pragma unroll
    for (int i = 0; i < 16; i++) {
        v[i] = r[lane + i * 32];
        s1 += v[i]; s2 += v[i] * v[i];
    }
    #pragma unroll
    for (int off = 16; off; off >>= 1) {
        s1 += __shfl_xor_sync(0xffffffffu, s1, off);
        s2 += __shfl_xor_sync(0xffffffffu, s2, off);
    }
    float mu   = s1 * (1.f / DD);
    float var  = s2 * (1.f / DD) - mu * mu;
    float rstd = rsqrtf(var + EPSV);
    float dot = 0.f;
    #pragma unroll
    for (int i = 0; i < 16; i++) {
        int d = lane + i * 32;
        float ln = (v[i] - mu) * rstd * g[d] + bb[d];
        dot += ln * w[d];
    }
    #pragma unroll
    for (int off = 16; off; off >>= 1) dot += __shfl_xor_sync(0xffffffffu, dot, off);
    if (lane == 0) out[row] = dot + bias[0];
}

// ---------------- launch ----------------
extern "C" void kernel_launch(void* const* d_in, const int* in_sizes, int n_in,
                              void* d_out, int out_size)
{
    const float* x        = (const float*)d_in[0];
    const float* z        = (const float*)d_in[1];
    const float* conv_w   = (const float*)d_in[2];
    const float* conv_b   = (const float*)d_in[3];
    const float* tok_g    = (const float*)d_in[4];
    const float* tok_b    = (const float*)d_in[5];
    const float* film_w   = (const float*)d_in[6];
    const float* film_b   = (const float*)d_in[7];
    const float* ln1_g    = (const float*)d_in[8];
    const float* ln1_b    = (const float*)d_in[9];
    const float* kqv_w    = (const float*)d_in[10];
    const float* kqv_b    = (const float*)d_in[11];
    const float* proj_w   = (const float*)d_in[12];
    const float* proj_b   = (const float*)d_in[13];
    const float* ln2_g    = (const float*)d_in[14];
    const float* ln2_b    = (const float*)d_in[15];
    const float* mlp_w1   = (const float*)d_in[16];
    const float* mlp_b1   = (const float*)d_in[17];
    const float* mlp_w2   = (const float*)d_in[18];
    const float* mlp_b2   = (const float*)d_in[19];
    const float* rs_attn  = (const float*)d_in[20];
    const float* rs_mlp   = (const float*)d_in[21];
    const float* head_g   = (const float*)d_in[22];
    const float* head_b   = (const float*)d_in[23];
    const float* head_w   = (const float*)d_in[24];
    const float* head_bia = (const float*)d_in[25];
    float* out = (float*)d_out;

    float *p_xi, *p_yv, *p_mid, *p_h;
    cudaGetSymbolAddress((void**)&p_xi,  g_xi);
    cudaGetSymbolAddress((void**)&p_yv,  g_yv);
    cudaGetSymbolAddress((void**)&p_mid, g_mid);
    cudaGetSymbolAddress((void**)&p_h,   g_h);

    transpose_w_kernel<<<(DD * K_CONV + 255) / 256, 256>>>(conv_w);
    rope_kernel<<<1, 1024>>>();
    conv_gemm_tc<<<dim3(8, 256), 256>>>(x, conv_b);
    pool_film_kernel<<<BT, 512>>>(z, film_w, film_b, tok_g, tok_b);

    for (int i = 0; i < LL; i++) {
        ln_kernel<<<128, 128>>>(p_h, ln1_g + i * DD, ln1_b + i * DD, p_xi);
        kqv_attn_kernel<<<dim3(8, 16), 128>>>(kqv_w + (size_t)i * DD * 3 * DD,
                                              kqv_b + i * 3 * DD);
        gemm_tc<2><<<dim3(8, 16), 128>>>(p_yv, proj_w + (size_t)i * DD * DD,
                                         proj_b + i * DD, p_h, rs_attn + i,
                                         p_h, BT, DD, DD);
        ln_kernel<<<128, 128>>>(p_h, ln2_g + i * DD, ln2_b + i * DD, p_xi);
        gemm_tc<1><<<dim3(32, 16), 128>>>(p_xi, mlp_w1 + (size_t)i * DD * 4 * DD,
                                          mlp_b1 + i * 4 * DD, nullptr, nullptr,
                                          p_mid, BT, 4 * DD, DD);
        gemm_tc<2><<<dim3(8, 16), 128>>>(p_mid, mlp_w2 + (size_t)i * 4 * DD * DD,
                                         mlp_b2 + i * DD, p_h, rs_mlp + i,
                                         p_h, BT, DD, 4 * DD);
    }
    head_kernel<<<64, 256>>>(head_g, head_b, head_w, head_bia, out);
}